// round 2
// baseline (speedup 1.0000x reference)
#include <cuda_runtime.h>
#include <math.h>
#include <stdint.h>

#define NTHR 256

// ---------------- device scratch (static, no allocation) ----------------
__device__ float g_w3j[11 * 125];       // per-instruction wigner3j, pre-scaled by PW[l3]
__device__ float g_W2T[11264 * 64];     // W2 transposed, pre-scaled by 1/8
__device__ float g_H[20000 * 64];       // weight-NN hidden activations

// irrep constants
constexpr int DIMS_[3] = {1, 3, 5};
constexpr int OFF_[3]  = {0, 32, 128};  // offsets into 288-dim feature
constexpr int SO_[3]   = {0, 1, 4};     // offsets into 9-dim sh
constexpr int KO_[3]   = {0, 1, 4};     // offsets into 9-slot accumulator

// ======================= wigner-3j setup (reference algorithm) =======================
__device__ __forceinline__ double dfact(int n) {
    double r = 1.0;
    for (int i = 2; i <= n; i++) r *= (double)i;
    return r;
}

__device__ void build_q(int l, double* qr, double* qi) {
    int D = 2 * l + 1;
    for (int i = 0; i < D * D; i++) { qr[i] = 0.0; qi[i] = 0.0; }
    const double s2 = 0.70710678118654752440;
    for (int m = -l; m < 0; m++) {
        qr[(l + m) * D + (l - m)] = s2;
        qi[(l + m) * D + (l + m)] = -s2;
    }
    qr[l * D + l] = 1.0;
    for (int m = 1; m <= l; m++) {
        double sg = (m & 1) ? -1.0 : 1.0;
        qr[(l + m) * D + (l + m)] = sg * s2;
        qi[(l + m) * D + (l - m)] = sg * s2;
    }
    // multiply by (-i)^l
    double fr, fi;
    switch (l & 3) {
        case 0: fr = 1;  fi = 0;  break;
        case 1: fr = 0;  fi = -1; break;
        case 2: fr = -1; fi = 0;  break;
        default: fr = 0; fi = 1;  break;
    }
    for (int i = 0; i < D * D; i++) {
        double r = qr[i], im = qi[i];
        qr[i] = r * fr - im * fi;
        qi[i] = r * fi + im * fr;
    }
}

__global__ void w3j_setup_kernel() {
    const int L1[11] = {0, 0, 0, 1, 1, 1, 1, 2, 2, 2, 2};
    const int L2[11] = {0, 1, 2, 0, 1, 1, 2, 0, 1, 2, 2};
    const int L3[11] = {0, 1, 2, 1, 0, 2, 1, 2, 1, 0, 2};
    int t = blockIdx.x;
    int j1 = L1[t], j2 = L2[t], j3 = L3[t];
    int d1 = 2 * j1 + 1, d2 = 2 * j2 + 1, d3 = 2 * j3 + 1;
    __shared__ double Cs[125];
    __shared__ double Q1r[25], Q1i[25], Q2r[25], Q2i[25], Q3r[25], Q3i[25];
    __shared__ double outv[125];
    __shared__ double scale_s;
    int tid = threadIdx.x;
    if (tid < 125) Cs[tid] = 0.0;
    if (tid == 0) {
        build_q(j1, Q1r, Q1i);
        build_q(j2, Q2r, Q2i);
        build_q(j3, Q3r, Q3i);
    }
    __syncthreads();
    if (tid < d1 * d2) {
        int m1 = tid / d2 - j1;
        int m2 = tid % d2 - j2;
        int m3 = m1 + m2;
        if (m3 >= -j3 && m3 <= j3) {
            int vmin = -j1 + j2 + m3;
            if (-j1 + m1 > vmin) vmin = -j1 + m1;
            if (vmin < 0) vmin = 0;
            int vmax = j2 + j3 + m1;
            if (j3 - j1 + j2 < vmax) vmax = j3 - j1 + j2;
            if (j3 + m3 < vmax) vmax = j3 + m3;
            double c = sqrt((double)(2 * j3 + 1) * dfact(j3 + j1 - j2) * dfact(j3 - j1 + j2) *
                            dfact(j1 + j2 - j3) * dfact(j3 + m3) * dfact(j3 - m3) /
                            (dfact(j1 + j2 + j3 + 1) * dfact(j1 - m1) * dfact(j1 + m1) *
                             dfact(j2 - m2) * dfact(j2 + m2)));
            double s = 0.0;
            for (int v = vmin; v <= vmax; v++) {
                double term = dfact(j2 + j3 + m1 - v) * dfact(j1 - m1 + v) /
                              (dfact(v) * dfact(j3 - j1 + j2 - v) * dfact(j3 + m3 - v) *
                               dfact(v + j1 - j2 - m3));
                if ((v + j2 + m2) & 1) term = -term;
                s += term;
            }
            Cs[((m1 + j1) * d2 + (m2 + j2)) * d3 + (m3 + j3)] = c * s;
        }
    }
    __syncthreads();
    int nel = d1 * d2 * d3;
    if (tid < nel) {
        int jj = tid / (d2 * d3);
        int ll = (tid / d3) % d2;
        int mm = tid % d3;
        double ar = 0.0;
        for (int i = 0; i < d1; i++)
            for (int k = 0; k < d2; k++)
                for (int n = 0; n < d3; n++) {
                    double cv = Cs[(i * d2 + k) * d3 + n];
                    if (cv == 0.0) continue;
                    double p1r = Q1r[i * d1 + jj], p1i = Q1i[i * d1 + jj];
                    double p2r = Q2r[k * d2 + ll], p2i = Q2i[k * d2 + ll];
                    double p3r = Q3r[n * d3 + mm], p3i = -Q3i[n * d3 + mm];
                    double t1r = p1r * p2r - p1i * p2i;
                    double t1i = p1r * p2i + p1i * p2r;
                    double t2r = t1r * p3r - t1i * p3i;
                    ar += t2r * cv;
                }
        outv[tid] = ar;
    }
    __syncthreads();
    if (tid == 0) {
        const double PWv[3] = {0.10206207261596575, 0.15309310892394862, 0.19764235376052370};
        double s = 0.0;
        for (int i = 0; i < nel; i++) s += outv[i] * outv[i];
        scale_s = PWv[j3] / sqrt(s);
    }
    __syncthreads();
    if (tid < nel) g_w3j[t * 125 + tid] = (float)(outv[tid] * scale_s);
}

// ======================= W2 transpose (+ 1/sqrt(64) fold) =======================
__global__ void w2t_kernel(const float* __restrict__ W2) {
    __shared__ float tile[32][33];
    int col0 = blockIdx.x * 32;
    int c0 = blockIdx.y * 32;
    int x = threadIdx.x, y = threadIdx.y;
    for (int yy = y; yy < 32; yy += 8)
        tile[yy][x] = W2[(c0 + yy) * 11264 + col0 + x] * 0.125f;
    __syncthreads();
    for (int yy = y; yy < 32; yy += 8)
        g_W2T[(col0 + yy) * 64 + (c0 + x)] = tile[x][yy];
}

// ======================= weight-NN hidden layer =======================
__global__ void h_kernel(const float* __restrict__ radial, const float* __restrict__ W1,
                         float cst, int E) {
    __shared__ float rs[4][64];
    int le = threadIdx.x >> 6, c = threadIdx.x & 63;
    int e = blockIdx.x * 4 + le;
    rs[le][c] = (e < E) ? radial[e * 64 + c] : 0.f;
    __syncthreads();
    float a = 0.f;
#pragma unroll
    for (int r = 0; r < 64; r++) a += rs[le][r] * W1[r * 64 + c];
    a *= 0.125f;  // 1/sqrt(64)
    float hv = cst * a / (1.f + expf(-a));
    if (e < E) g_H[e * 64 + c] = hv;
}

// ======================= self-connection (writes d_out, clears poison) =======================
__global__ void sc_kernel(const float* __restrict__ nf, const float* __restrict__ w0,
                          const float* __restrict__ w1, const float* __restrict__ w2,
                          float* __restrict__ out) {
    __shared__ float xrow[288];
    int n = blockIdx.x;
    int t = threadIdx.x;
    xrow[t] = nf[n * 288 + t];
    __syncthreads();
    int O, d, wch, k;
    const float* W;
    if (t < 32)       { O = 0;   d = 1; wch = t;          k = 0;            W = w0; }
    else if (t < 128) { int r = t - 32;  O = 32;  d = 3; wch = r / 3; k = r - wch * 3; W = w1; }
    else              { int r = t - 128; O = 128; d = 5; wch = r / 5; k = r - wch * 5; W = w2; }
    float a = 0.f;
#pragma unroll
    for (int u = 0; u < 32; u++) a += xrow[O + u * d + k] * W[u * 32 + wch];
    out[n * 288 + t] = a * 0.17677669529663687f;  // 1/sqrt(32)
}

// ======================= fused message kernel =======================
// Block = 256 threads, 32 edges. Thread (g,w): g=tid/32, w=tid%32 owns edges {4g..4g+3} x out-channel w.
template <int D1, int D2, int D3, int SO2, int O1, int KO, int W3OFF, int COFF>
__device__ __forceinline__ void process_ins(float* __restrict__ xs, const float* __restrict__ hs,
                                            float* __restrict__ zs, float* __restrict__ ss,
                                            const float* __restrict__ shT, float (&acc)[4][9],
                                            int tid, int w, int ebase) {
    __syncthreads();  // protect ss/zs reuse
    // s[e,i,k] = sum_j w3j[i,j,k] * sh[e,j]
    for (int idx = tid; idx < 32 * D1 * D3; idx += NTHR) {
        int e = idx & 31;
        int r = idx >> 5;
        int i = r / D3;
        int k = r - i * D3;
        float a = 0.f;
#pragma unroll
        for (int j = 0; j < D2; j++)
            a += g_w3j[W3OFF + (i * D2 + j) * D3 + k] * shT[(SO2 + j) * 33 + e];
        ss[(i * D3 + k) * 33 + e] = a;
    }
    __syncthreads();
    // z[e,u,k] = sum_i x[e,u,i] * s[e,i,k]
    for (int idx = tid; idx < 1024; idx += NTHR) {
        int e = idx & 31;
        int u = idx >> 5;
        float xv[D1];
#pragma unroll
        for (int i = 0; i < D1; i++) xv[i] = xs[(O1 + u * D1 + i) * 33 + e];
#pragma unroll
        for (int k = 0; k < D3; k++) {
            float z = 0.f;
#pragma unroll
            for (int i = 0; i < D1; i++) z += xv[i] * ss[(i * D3 + k) * 33 + e];
            zs[(u * D3 + k) * 33 + e] = z;
        }
    }
    __syncthreads();
    // GEMM: wv[e,w] = h[e,:] . W2T[col,:], consumed immediately: acc[e,w,k] += wv * z[e,u,k]
    const float4* __restrict__ h0 = (const float4*)(hs + (ebase + 0) * 64);
    const float4* __restrict__ h1 = (const float4*)(hs + (ebase + 1) * 64);
    const float4* __restrict__ h2 = (const float4*)(hs + (ebase + 2) * 64);
    const float4* __restrict__ h3 = (const float4*)(hs + (ebase + 3) * 64);
#pragma unroll 1
    for (int u = 0; u < 32; u++) {
        const float4* __restrict__ wrow = (const float4*)(g_W2T + (COFF + u * 32 + w) * 64);
        float wv0 = 0.f, wv1 = 0.f, wv2 = 0.f, wv3 = 0.f;
#pragma unroll
        for (int c = 0; c < 16; c++) {
            float4 q = __ldg(wrow + c);
            float4 a0 = h0[c], a1 = h1[c], a2 = h2[c], a3 = h3[c];
            wv0 += q.x * a0.x + q.y * a0.y + q.z * a0.z + q.w * a0.w;
            wv1 += q.x * a1.x + q.y * a1.y + q.z * a1.z + q.w * a1.w;
            wv2 += q.x * a2.x + q.y * a2.y + q.z * a2.z + q.w * a2.w;
            wv3 += q.x * a3.x + q.y * a3.y + q.z * a3.z + q.w * a3.w;
        }
#pragma unroll
        for (int k = 0; k < D3; k++) {
            float z0 = zs[(u * D3 + k) * 33 + ebase + 0];
            float z1 = zs[(u * D3 + k) * 33 + ebase + 1];
            float z2 = zs[(u * D3 + k) * 33 + ebase + 2];
            float z3 = zs[(u * D3 + k) * 33 + ebase + 3];
            acc[0][KO + k] += wv0 * z0;
            acc[1][KO + k] += wv1 * z1;
            acc[2][KO + k] += wv2 * z2;
            acc[3][KO + k] += wv3 * z3;
        }
    }
}

#define PINS(IDX, A, B, Cc)                                                                   \
    process_ins<DIMS_[A], DIMS_[B], DIMS_[Cc], SO_[B], OFF_[A], KO_[Cc], IDX * 125,           \
                IDX * 1024>(xs, hs, zs, ss, shT, acc, tid, w, ebase)

__global__ void __launch_bounds__(NTHR)
msg_kernel(const float* __restrict__ nf, const int* __restrict__ ei,
           const float* __restrict__ shg, float* __restrict__ out, int E) {
    extern __shared__ float smem[];
    float* xs  = smem;            // 288*33 = 9504 (transposed, padded)
    float* hs  = xs + 9504;       // 32*64  = 2048
    float* zs  = hs + 2048;       // 32*5*33 = 5280
    float* ss  = zs + 5280;       // 25*33 = 825
    float* shT = ss + 825;        // 9*33 = 297
    int* srcdst = (int*)(shT + 297);  // 64 ints: [0:32)=src, [32:64)=dst
    int tid = threadIdx.x;
    int e0 = blockIdx.x * 32;

    if (tid < 64) {
        int e = e0 + (tid & 31);
        int which = tid >> 5;
        srcdst[tid] = (e < E) ? ei[which * E + e] : 0;
    }
    __syncthreads();
    for (int idx = tid; idx < 32 * 288; idx += NTHR) {
        int e = idx / 288;
        int c = idx - e * 288;
        xs[c * 33 + e] = (e0 + e < E) ? nf[srcdst[e] * 288 + c] : 0.f;
    }
    for (int idx = tid; idx < 32 * 64; idx += NTHR) {
        int e = idx >> 6;
        int c = idx & 63;
        hs[e * 64 + c] = (e0 + e < E) ? g_H[(e0 + e) * 64 + c] : 0.f;
    }
    for (int idx = tid; idx < 32 * 9; idx += NTHR) {
        int e = idx & 31;
        int j = idx >> 5;
        shT[j * 33 + e] = (e0 + e < E) ? shg[(e0 + e) * 9 + j] : 0.f;
    }
    // (first process_ins's leading __syncthreads covers the load phase)

    int w = tid & 31;
    int ebase = (tid >> 5) * 4;
    float acc[4][9];
#pragma unroll
    for (int p = 0; p < 4; p++)
#pragma unroll
        for (int k = 0; k < 9; k++) acc[p][k] = 0.f;

    PINS(0, 0, 0, 0); PINS(1, 0, 1, 1); PINS(2, 0, 2, 2); PINS(3, 1, 0, 1);
    PINS(4, 1, 1, 0); PINS(5, 1, 1, 2); PINS(6, 1, 2, 1); PINS(7, 2, 0, 2);
    PINS(8, 2, 1, 1); PINS(9, 2, 2, 0); PINS(10, 2, 2, 2);

    const float inv = 0.31622776601683794f;  // 1/sqrt(NUM_NEIGHBORS)
#pragma unroll
    for (int p = 0; p < 4; p++) {
        int e = ebase + p;
        if (e0 + e >= E) continue;
        int node = srcdst[32 + e];
        float* op = out + node * 288;
        atomicAdd(op + w, inv * acc[p][0]);
#pragma unroll
        for (int k = 0; k < 3; k++) atomicAdd(op + 32 + w * 3 + k, inv * acc[p][1 + k]);
#pragma unroll
        for (int k = 0; k < 5; k++) atomicAdd(op + 128 + w * 5 + k, inv * acc[p][4 + k]);
    }
}

// ======================= host: numpy RandomState(0) SILU_CST reproduction =======================
namespace {
struct NpRng {
    uint32_t mt[624];
    int mti;
    bool has_g;
    double g;
};
inline void rng_seed(NpRng& s, uint32_t sd) {
    s.mt[0] = sd;
    for (int i = 1; i < 624; i++)
        s.mt[i] = 1812433253u * (s.mt[i - 1] ^ (s.mt[i - 1] >> 30)) + (uint32_t)i;
    s.mti = 624;
    s.has_g = false;
    s.g = 0.0;
}
inline uint32_t rng_u32(NpRng& s) {
    if (s.mti >= 624) {
        for (int i = 0; i < 624; i++) {
            uint32_t y = (s.mt[i] & 0x80000000u) | (s.mt[(i + 1) % 624] & 0x7fffffffu);
            s.mt[i] = s.mt[(i + 397) % 624] ^ (y >> 1) ^ ((y & 1u) ? 0x9908b0dfu : 0u);
        }
        s.mti = 0;
    }
    uint32_t y = s.mt[s.mti++];
    y ^= y >> 11;
    y ^= (y << 7) & 0x9d2c5680u;
    y ^= (y << 15) & 0xefc60000u;
    y ^= y >> 18;
    return y;
}
inline double rng_double(NpRng& s) {
    uint32_t a = rng_u32(s) >> 5;
    uint32_t b = rng_u32(s) >> 6;
    return ((double)a * 67108864.0 + (double)b) / 9007199254740992.0;
}
inline double rng_gauss(NpRng& s) {
    if (s.has_g) {
        s.has_g = false;
        return s.g;
    }
    double x1, x2, r2;
    do {
        x1 = 2.0 * rng_double(s) - 1.0;
        x2 = 2.0 * rng_double(s) - 1.0;
        r2 = x1 * x1 + x2 * x2;
    } while (r2 >= 1.0 || r2 == 0.0);
    double f = sqrt(-2.0 * log(r2) / r2);
    s.g = f * x1;
    s.has_g = true;
    return f * x2;
}
inline double compute_silu_cst() {
    NpRng s;
    rng_seed(s, 0u);
    double sum = 0.0;
    for (int i = 0; i < 1000000; i++) {
        double z = rng_gauss(s);
        double sl = z / (1.0 + exp(-z));
        sum += sl * sl;
    }
    return 1.0 / sqrt(sum / 1000000.0);
}
}  // namespace

// ======================= launch =======================
extern "C" void kernel_launch(void* const* d_in, const int* in_sizes, int n_in,
                              void* d_out, int out_size) {
    const float* nf     = (const float*)d_in[0];
    const int*   ei     = (const int*)d_in[1];
    const float* sh     = (const float*)d_in[2];
    const float* radial = (const float*)d_in[3];
    const float* W1     = (const float*)d_in[4];
    const float* W2     = (const float*)d_in[5];
    const float* Wsc0   = (const float*)d_in[6];
    const float* Wsc1   = (const float*)d_in[7];
    const float* Wsc2   = (const float*)d_in[8];
    float* out = (float*)d_out;
    int N = in_sizes[0] / 288;
    int E = in_sizes[1] / 2;

    float cst = (float)compute_silu_cst();

    const size_t SMEM = (9504 + 2048 + 5280 + 825 + 297) * 4 + 64 * 4;  // 72072 B
    cudaFuncSetAttribute(msg_kernel, cudaFuncAttributeMaxDynamicSharedMemorySize, (int)SMEM);

    w3j_setup_kernel<<<11, 128>>>();
    w2t_kernel<<<dim3(352, 2), dim3(32, 8)>>>(W2);
    h_kernel<<<(E + 3) / 4, 256>>>(radial, W1, cst, E);
    sc_kernel<<<N, 288>>>(nf, Wsc0, Wsc1, Wsc2, out);
    msg_kernel<<<(E + 31) / 32, NTHR, SMEM>>>(nf, ei, sh, out, E);
}

// round 3
// speedup vs baseline: 2.5489x; 2.5489x over previous
#include <cuda_runtime.h>
#include <math.h>
#include <stdint.h>

#define NTHR 256

// ---------------- device scratch (static, no allocation) ----------------
__device__ float g_w3j[11 * 125];       // per-instruction wigner3j, pre-scaled by PW[l3]
__device__ float g_W2P[11264 * 64];     // W2 relayout [ins][u][c/4][w][c%4], pre-scaled by 1/8
__device__ float g_H[20000 * 64];       // weight-NN hidden activations

// irrep constants
constexpr int DIMS_[3] = {1, 3, 5};
constexpr int OFF_[3]  = {0, 32, 128};  // offsets into 288-dim feature
constexpr int SO_[3]   = {0, 1, 4};     // offsets into 9-dim sh
constexpr int KO_[3]   = {0, 1, 4};     // offsets into 9-slot accumulator

// ======================= wigner-3j setup (reference algorithm) =======================
__device__ __forceinline__ double dfact(int n) {
    double r = 1.0;
    for (int i = 2; i <= n; i++) r *= (double)i;
    return r;
}

__device__ void build_q(int l, double* qr, double* qi) {
    int D = 2 * l + 1;
    for (int i = 0; i < D * D; i++) { qr[i] = 0.0; qi[i] = 0.0; }
    const double s2 = 0.70710678118654752440;
    for (int m = -l; m < 0; m++) {
        qr[(l + m) * D + (l - m)] = s2;
        qi[(l + m) * D + (l + m)] = -s2;
    }
    qr[l * D + l] = 1.0;
    for (int m = 1; m <= l; m++) {
        double sg = (m & 1) ? -1.0 : 1.0;
        qr[(l + m) * D + (l + m)] = sg * s2;
        qi[(l + m) * D + (l - m)] = sg * s2;
    }
    double fr, fi;
    switch (l & 3) {
        case 0: fr = 1;  fi = 0;  break;
        case 1: fr = 0;  fi = -1; break;
        case 2: fr = -1; fi = 0;  break;
        default: fr = 0; fi = 1;  break;
    }
    for (int i = 0; i < D * D; i++) {
        double r = qr[i], im = qi[i];
        qr[i] = r * fr - im * fi;
        qi[i] = r * fi + im * fr;
    }
}

__global__ void w3j_setup_kernel() {
    const int L1[11] = {0, 0, 0, 1, 1, 1, 1, 2, 2, 2, 2};
    const int L2[11] = {0, 1, 2, 0, 1, 1, 2, 0, 1, 2, 2};
    const int L3[11] = {0, 1, 2, 1, 0, 2, 1, 2, 1, 0, 2};
    int t = blockIdx.x;
    int j1 = L1[t], j2 = L2[t], j3 = L3[t];
    int d1 = 2 * j1 + 1, d2 = 2 * j2 + 1, d3 = 2 * j3 + 1;
    __shared__ double Cs[125];
    __shared__ double Q1r[25], Q1i[25], Q2r[25], Q2i[25], Q3r[25], Q3i[25];
    __shared__ double outv[125];
    __shared__ double scale_s;
    int tid = threadIdx.x;
    if (tid < 125) Cs[tid] = 0.0;
    if (tid == 0) {
        build_q(j1, Q1r, Q1i);
        build_q(j2, Q2r, Q2i);
        build_q(j3, Q3r, Q3i);
    }
    __syncthreads();
    if (tid < d1 * d2) {
        int m1 = tid / d2 - j1;
        int m2 = tid % d2 - j2;
        int m3 = m1 + m2;
        if (m3 >= -j3 && m3 <= j3) {
            int vmin = -j1 + j2 + m3;
            if (-j1 + m1 > vmin) vmin = -j1 + m1;
            if (vmin < 0) vmin = 0;
            int vmax = j2 + j3 + m1;
            if (j3 - j1 + j2 < vmax) vmax = j3 - j1 + j2;
            if (j3 + m3 < vmax) vmax = j3 + m3;
            double c = sqrt((double)(2 * j3 + 1) * dfact(j3 + j1 - j2) * dfact(j3 - j1 + j2) *
                            dfact(j1 + j2 - j3) * dfact(j3 + m3) * dfact(j3 - m3) /
                            (dfact(j1 + j2 + j3 + 1) * dfact(j1 - m1) * dfact(j1 + m1) *
                             dfact(j2 - m2) * dfact(j2 + m2)));
            double s = 0.0;
            for (int v = vmin; v <= vmax; v++) {
                double term = dfact(j2 + j3 + m1 - v) * dfact(j1 - m1 + v) /
                              (dfact(v) * dfact(j3 - j1 + j2 - v) * dfact(j3 + m3 - v) *
                               dfact(v + j1 - j2 - m3));
                if ((v + j2 + m2) & 1) term = -term;
                s += term;
            }
            Cs[((m1 + j1) * d2 + (m2 + j2)) * d3 + (m3 + j3)] = c * s;
        }
    }
    __syncthreads();
    int nel = d1 * d2 * d3;
    if (tid < nel) {
        int jj = tid / (d2 * d3);
        int ll = (tid / d3) % d2;
        int mm = tid % d3;
        double ar = 0.0;
        for (int i = 0; i < d1; i++)
            for (int k = 0; k < d2; k++)
                for (int n = 0; n < d3; n++) {
                    double cv = Cs[(i * d2 + k) * d3 + n];
                    if (cv == 0.0) continue;
                    double p1r = Q1r[i * d1 + jj], p1i = Q1i[i * d1 + jj];
                    double p2r = Q2r[k * d2 + ll], p2i = Q2i[k * d2 + ll];
                    double p3r = Q3r[n * d3 + mm], p3i = -Q3i[n * d3 + mm];
                    double t1r = p1r * p2r - p1i * p2i;
                    double t1i = p1r * p2i + p1i * p2r;
                    double t2r = t1r * p3r - t1i * p3i;
                    ar += t2r * cv;
                }
        outv[tid] = ar;
    }
    __syncthreads();
    if (tid == 0) {
        const double PWv[3] = {0.10206207261596575, 0.15309310892394862, 0.19764235376052370};
        double s = 0.0;
        for (int i = 0; i < nel; i++) s += outv[i] * outv[i];
        scale_s = PWv[j3] / sqrt(s);
    }
    __syncthreads();
    if (tid < nel) g_w3j[t * 125 + tid] = (float)(outv[tid] * scale_s);
}

// ======================= W2 relayout (+ 1/sqrt(64) fold) =======================
// src: W2[c][col] with col = ins*1024 + u*32 + w  (c in [0,64), row-major [64,11264])
// dst: g_W2P[ ((col/32)*16 + c/4)*128 + (col%32)*4 + (c%4) ]
//      i.e. float4 tiles: [ins*32+u][c4][w] with 4 consecutive c packed per lane.
__global__ void w2p_kernel(const float* __restrict__ W2) {
    int idx = blockIdx.x * 256 + threadIdx.x;
    if (idx >= 64 * 11264) return;
    int c = idx / 11264;
    int col = idx - c * 11264;
    int dst = ((col >> 5) * 16 + (c >> 2)) * 128 + ((col & 31) << 2) + (c & 3);
    g_W2P[dst] = W2[idx] * 0.125f;
}

// ======================= weight-NN hidden layer =======================
__global__ void h_kernel(const float* __restrict__ radial, const float* __restrict__ W1,
                         float cst, int E) {
    __shared__ float rs[4][64];
    int le = threadIdx.x >> 6, c = threadIdx.x & 63;
    int e = blockIdx.x * 4 + le;
    rs[le][c] = (e < E) ? radial[e * 64 + c] : 0.f;
    __syncthreads();
    float a = 0.f;
#pragma unroll
    for (int r = 0; r < 64; r++) a += rs[le][r] * W1[r * 64 + c];
    a *= 0.125f;  // 1/sqrt(64)
    float hv = cst * a / (1.f + expf(-a));
    if (e < E) g_H[e * 64 + c] = hv;
}

// ======================= self-connection (writes d_out, clears poison) =======================
__global__ void sc_kernel(const float* __restrict__ nf, const float* __restrict__ w0,
                          const float* __restrict__ w1, const float* __restrict__ w2,
                          float* __restrict__ out) {
    __shared__ float xrow[288];
    int n = blockIdx.x;
    int t = threadIdx.x;
    xrow[t] = nf[n * 288 + t];
    __syncthreads();
    int O, d, wch, k;
    const float* W;
    if (t < 32)       { O = 0;   d = 1; wch = t;          k = 0;            W = w0; }
    else if (t < 128) { int r = t - 32;  O = 32;  d = 3; wch = r / 3; k = r - wch * 3; W = w1; }
    else              { int r = t - 128; O = 128; d = 5; wch = r / 5; k = r - wch * 5; W = w2; }
    float a = 0.f;
#pragma unroll
    for (int u = 0; u < 32; u++) a += xrow[O + u * d + k] * W[u * 32 + wch];
    out[n * 288 + t] = a * 0.17677669529663687f;  // 1/sqrt(32)
}

// ======================= fused message kernel =======================
// Block = 256 threads, 32 edges. Thread (g,w): g=tid/32, w=tid%32 owns edges {4g..4g+3} x out-channel w.
// PBASE is in float4 units: ins_idx * 32u * 16c4 * 32w = ins_idx * 16384.
template <int D1, int D2, int D3, int SO2, int O1, int KO, int W3OFF, int PBASE>
__device__ __forceinline__ void process_ins(float* __restrict__ xs, const float* __restrict__ hs,
                                            float* __restrict__ zs, float* __restrict__ ss,
                                            const float* __restrict__ shT, float (&acc)[4][9],
                                            int tid, int w, int ebase) {
    __syncthreads();  // protect ss/zs reuse
    // s[e,i,k] = sum_j w3j[i,j,k] * sh[e,j]
    for (int idx = tid; idx < 32 * D1 * D3; idx += NTHR) {
        int e = idx & 31;
        int r = idx >> 5;
        int i = r / D3;
        int k = r - i * D3;
        float a = 0.f;
#pragma unroll
        for (int j = 0; j < D2; j++)
            a += g_w3j[W3OFF + (i * D2 + j) * D3 + k] * shT[(SO2 + j) * 33 + e];
        ss[(i * D3 + k) * 33 + e] = a;
    }
    __syncthreads();
    // z[e,u,k] = sum_i x[e,u,i] * s[e,i,k]
    for (int idx = tid; idx < 1024; idx += NTHR) {
        int e = idx & 31;
        int u = idx >> 5;
        float xv[D1];
#pragma unroll
        for (int i = 0; i < D1; i++) xv[i] = xs[(O1 + u * D1 + i) * 33 + e];
#pragma unroll
        for (int k = 0; k < D3; k++) {
            float z = 0.f;
#pragma unroll
            for (int i = 0; i < D1; i++) z += xv[i] * ss[(i * D3 + k) * 33 + e];
            zs[(u * D3 + k) * 33 + e] = z;
        }
    }
    __syncthreads();
    // GEMM: wv[e,w] = h[e,:] . W2P[ins,u,:,w], consumed immediately: acc[e,w,k] += wv * z[e,u,k]
    const float4* __restrict__ h0 = (const float4*)(hs + (ebase + 0) * 64);
    const float4* __restrict__ h1 = (const float4*)(hs + (ebase + 1) * 64);
    const float4* __restrict__ h2 = (const float4*)(hs + (ebase + 2) * 64);
    const float4* __restrict__ h3 = (const float4*)(hs + (ebase + 3) * 64);
#pragma unroll 1
    for (int u = 0; u < 32; u++) {
        // lanes (w) read consecutive float4s: coalesced, 4 wavefronts per LDG.128
        const float4* __restrict__ W4 = ((const float4*)g_W2P) + PBASE + u * 512 + w;
        float wv0 = 0.f, wv1 = 0.f, wv2 = 0.f, wv3 = 0.f;
#pragma unroll
        for (int c = 0; c < 16; c++) {
            float4 q = __ldg(W4 + c * 32);
            float4 a0 = h0[c], a1 = h1[c], a2 = h2[c], a3 = h3[c];
            wv0 += q.x * a0.x + q.y * a0.y + q.z * a0.z + q.w * a0.w;
            wv1 += q.x * a1.x + q.y * a1.y + q.z * a1.z + q.w * a1.w;
            wv2 += q.x * a2.x + q.y * a2.y + q.z * a2.z + q.w * a2.w;
            wv3 += q.x * a3.x + q.y * a3.y + q.z * a3.z + q.w * a3.w;
        }
#pragma unroll
        for (int k = 0; k < D3; k++) {
            float z0 = zs[(u * D3 + k) * 33 + ebase + 0];
            float z1 = zs[(u * D3 + k) * 33 + ebase + 1];
            float z2 = zs[(u * D3 + k) * 33 + ebase + 2];
            float z3 = zs[(u * D3 + k) * 33 + ebase + 3];
            acc[0][KO + k] += wv0 * z0;
            acc[1][KO + k] += wv1 * z1;
            acc[2][KO + k] += wv2 * z2;
            acc[3][KO + k] += wv3 * z3;
        }
    }
}

#define PINS(IDX, A, B, Cc)                                                                   \
    process_ins<DIMS_[A], DIMS_[B], DIMS_[Cc], SO_[B], OFF_[A], KO_[Cc], IDX * 125,           \
                IDX * 16384>(xs, hs, zs, ss, shT, acc, tid, w, ebase)

__global__ void __launch_bounds__(NTHR)
msg_kernel(const float* __restrict__ nf, const int* __restrict__ ei,
           const float* __restrict__ shg, float* __restrict__ out, int E) {
    extern __shared__ float smem[];
    float* xs  = smem;            // 288*33 = 9504 (transposed, padded)
    float* hs  = xs + 9504;       // 32*64  = 2048
    float* zs  = hs + 2048;       // 32*5*33 = 5280
    float* ss  = zs + 5280;       // 25*33 = 825
    float* shT = ss + 825;        // 9*33 = 297
    int* srcdst = (int*)(shT + 297);  // 64 ints: [0:32)=src, [32:64)=dst
    int tid = threadIdx.x;
    int e0 = blockIdx.x * 32;

    if (tid < 64) {
        int e = e0 + (tid & 31);
        int which = tid >> 5;
        srcdst[tid] = (e < E) ? ei[which * E + e] : 0;
    }
    __syncthreads();
    for (int idx = tid; idx < 32 * 288; idx += NTHR) {
        int e = idx / 288;
        int c = idx - e * 288;
        xs[c * 33 + e] = (e0 + e < E) ? nf[srcdst[e] * 288 + c] : 0.f;
    }
    for (int idx = tid; idx < 32 * 64; idx += NTHR) {
        int e = idx >> 6;
        int c = idx & 63;
        hs[e * 64 + c] = (e0 + e < E) ? g_H[(e0 + e) * 64 + c] : 0.f;
    }
    for (int idx = tid; idx < 32 * 9; idx += NTHR) {
        int e = idx & 31;
        int j = idx >> 5;
        shT[j * 33 + e] = (e0 + e < E) ? shg[(e0 + e) * 9 + j] : 0.f;
    }
    // (first process_ins's leading __syncthreads covers the load phase)

    int w = tid & 31;
    int ebase = (tid >> 5) * 4;
    float acc[4][9];
#pragma unroll
    for (int p = 0; p < 4; p++)
#pragma unroll
        for (int k = 0; k < 9; k++) acc[p][k] = 0.f;

    PINS(0, 0, 0, 0); PINS(1, 0, 1, 1); PINS(2, 0, 2, 2); PINS(3, 1, 0, 1);
    PINS(4, 1, 1, 0); PINS(5, 1, 1, 2); PINS(6, 1, 2, 1); PINS(7, 2, 0, 2);
    PINS(8, 2, 1, 1); PINS(9, 2, 2, 0); PINS(10, 2, 2, 2);

    const float inv = 0.31622776601683794f;  // 1/sqrt(NUM_NEIGHBORS)
#pragma unroll
    for (int p = 0; p < 4; p++) {
        int e = ebase + p;
        if (e0 + e >= E) continue;
        int node = srcdst[32 + e];
        float* op = out + node * 288;
        atomicAdd(op + w, inv * acc[p][0]);
#pragma unroll
        for (int k = 0; k < 3; k++) atomicAdd(op + 32 + w * 3 + k, inv * acc[p][1 + k]);
#pragma unroll
        for (int k = 0; k < 5; k++) atomicAdd(op + 128 + w * 5 + k, inv * acc[p][4 + k]);
    }
}

// ======================= host: numpy RandomState(0) SILU_CST reproduction =======================
namespace {
struct NpRng {
    uint32_t mt[624];
    int mti;
    bool has_g;
    double g;
};
inline void rng_seed(NpRng& s, uint32_t sd) {
    s.mt[0] = sd;
    for (int i = 1; i < 624; i++)
        s.mt[i] = 1812433253u * (s.mt[i - 1] ^ (s.mt[i - 1] >> 30)) + (uint32_t)i;
    s.mti = 624;
    s.has_g = false;
    s.g = 0.0;
}
inline uint32_t rng_u32(NpRng& s) {
    if (s.mti >= 624) {
        for (int i = 0; i < 624; i++) {
            uint32_t y = (s.mt[i] & 0x80000000u) | (s.mt[(i + 1) % 624] & 0x7fffffffu);
            s.mt[i] = s.mt[(i + 397) % 624] ^ (y >> 1) ^ ((y & 1u) ? 0x9908b0dfu : 0u);
        }
        s.mti = 0;
    }
    uint32_t y = s.mt[s.mti++];
    y ^= y >> 11;
    y ^= (y << 7) & 0x9d2c5680u;
    y ^= (y << 15) & 0xefc60000u;
    y ^= y >> 18;
    return y;
}
inline double rng_double(NpRng& s) {
    uint32_t a = rng_u32(s) >> 5;
    uint32_t b = rng_u32(s) >> 6;
    return ((double)a * 67108864.0 + (double)b) / 9007199254740992.0;
}
inline double rng_gauss(NpRng& s) {
    if (s.has_g) {
        s.has_g = false;
        return s.g;
    }
    double x1, x2, r2;
    do {
        x1 = 2.0 * rng_double(s) - 1.0;
        x2 = 2.0 * rng_double(s) - 1.0;
        r2 = x1 * x1 + x2 * x2;
    } while (r2 >= 1.0 || r2 == 0.0);
    double f = sqrt(-2.0 * log(r2) / r2);
    s.g = f * x1;
    s.has_g = true;
    return f * x2;
}
inline double compute_silu_cst() {
    NpRng s;
    rng_seed(s, 0u);
    double sum = 0.0;
    for (int i = 0; i < 1000000; i++) {
        double z = rng_gauss(s);
        double sl = z / (1.0 + exp(-z));
        sum += sl * sl;
    }
    return 1.0 / sqrt(sum / 1000000.0);
}
}  // namespace

// ======================= launch =======================
extern "C" void kernel_launch(void* const* d_in, const int* in_sizes, int n_in,
                              void* d_out, int out_size) {
    const float* nf     = (const float*)d_in[0];
    const int*   ei     = (const int*)d_in[1];
    const float* sh     = (const float*)d_in[2];
    const float* radial = (const float*)d_in[3];
    const float* W1     = (const float*)d_in[4];
    const float* W2     = (const float*)d_in[5];
    const float* Wsc0   = (const float*)d_in[6];
    const float* Wsc1   = (const float*)d_in[7];
    const float* Wsc2   = (const float*)d_in[8];
    float* out = (float*)d_out;
    int N = in_sizes[0] / 288;
    int E = in_sizes[1] / 2;

    float cst = (float)compute_silu_cst();

    const size_t SMEM = (9504 + 2048 + 5280 + 825 + 297) * 4 + 64 * 4;  // 72072 B
    cudaFuncSetAttribute(msg_kernel, cudaFuncAttributeMaxDynamicSharedMemorySize, (int)SMEM);

    w3j_setup_kernel<<<11, 128>>>();
    w2p_kernel<<<(64 * 11264 + 255) / 256, 256>>>(W2);
    h_kernel<<<(E + 3) / 4, 256>>>(radial, W1, cst, E);
    sc_kernel<<<N, 288>>>(nf, Wsc0, Wsc1, Wsc2, out);
    msg_kernel<<<(E + 31) / 32, NTHR, SMEM>>>(nf, ei, sh, out, E);
}

// round 5
// speedup vs baseline: 10.4487x; 4.0993x over previous
#include <cuda_runtime.h>
#include <math.h>
#include <stdint.h>

#define NTHR 256

// ---------------- device scratch (static, no allocation) ----------------
__device__ float g_w3j[11 * 125];        // per-instruction wigner3j, pre-scaled by PW[l3]
__device__ float4 g_W2P[11 * 32 * 4 * 4 * 32];  // W2 in tf32 B-fragment layout (2.88 MB)
__device__ float g_H[20000 * 64];        // weight-NN hidden activations (tf32-rounded)

// irrep constants
constexpr int DIMS_[3] = {1, 3, 5};
constexpr int OFF_[3]  = {0, 32, 128};  // offsets into 288-dim feature
constexpr int SO_[3]   = {0, 1, 4};     // offsets into 9-dim sh
constexpr int KO_[3]   = {0, 1, 4};     // offsets into 9-slot accumulator

__device__ __forceinline__ float to_tf32(float v) {
    uint32_t r;
    asm("cvt.rna.tf32.f32 %0, %1;" : "=r"(r) : "f"(v));
    return __uint_as_float(r);
}

// tf32 m16n8k8 MMA, D += A*B
__device__ __forceinline__ void mma_tf32(float* d, const float* a, float b0, float b1) {
    asm volatile(
        "mma.sync.aligned.m16n8k8.row.col.f32.tf32.tf32.f32 "
        "{%0,%1,%2,%3}, {%4,%5,%6,%7}, {%8,%9}, {%0,%1,%2,%3};\n"
        : "+f"(d[0]), "+f"(d[1]), "+f"(d[2]), "+f"(d[3])
        : "r"(__float_as_uint(a[0])), "r"(__float_as_uint(a[1])),
          "r"(__float_as_uint(a[2])), "r"(__float_as_uint(a[3])),
          "r"(__float_as_uint(b0)), "r"(__float_as_uint(b1)));
}

// ======================= wigner-3j setup (reference algorithm) =======================
__device__ __forceinline__ double dfact(int n) {
    double r = 1.0;
    for (int i = 2; i <= n; i++) r *= (double)i;
    return r;
}

__device__ void build_q(int l, double* qr, double* qi) {
    int D = 2 * l + 1;
    for (int i = 0; i < D * D; i++) { qr[i] = 0.0; qi[i] = 0.0; }
    const double s2 = 0.70710678118654752440;
    for (int m = -l; m < 0; m++) {
        qr[(l + m) * D + (l - m)] = s2;
        qi[(l + m) * D + (l + m)] = -s2;
    }
    qr[l * D + l] = 1.0;
    for (int m = 1; m <= l; m++) {
        double sg = (m & 1) ? -1.0 : 1.0;
        qr[(l + m) * D + (l + m)] = sg * s2;
        qi[(l + m) * D + (l - m)] = sg * s2;
    }
    double fr, fi;
    switch (l & 3) {
        case 0: fr = 1;  fi = 0;  break;
        case 1: fr = 0;  fi = -1; break;
        case 2: fr = -1; fi = 0;  break;
        default: fr = 0; fi = 1;  break;
    }
    for (int i = 0; i < D * D; i++) {
        double r = qr[i], im = qi[i];
        qr[i] = r * fr - im * fi;
        qi[i] = r * fi + im * fr;
    }
}

__global__ void w3j_setup_kernel() {
    const int L1[11] = {0, 0, 0, 1, 1, 1, 1, 2, 2, 2, 2};
    const int L2[11] = {0, 1, 2, 0, 1, 1, 2, 0, 1, 2, 2};
    const int L3[11] = {0, 1, 2, 1, 0, 2, 1, 2, 1, 0, 2};
    int t = blockIdx.x;
    int j1 = L1[t], j2 = L2[t], j3 = L3[t];
    int d1 = 2 * j1 + 1, d2 = 2 * j2 + 1, d3 = 2 * j3 + 1;
    __shared__ double Cs[125];
    __shared__ double Q1r[25], Q1i[25], Q2r[25], Q2i[25], Q3r[25], Q3i[25];
    __shared__ double outv[125];
    __shared__ double scale_s;
    int tid = threadIdx.x;
    if (tid < 125) Cs[tid] = 0.0;
    if (tid == 0) {
        build_q(j1, Q1r, Q1i);
        build_q(j2, Q2r, Q2i);
        build_q(j3, Q3r, Q3i);
    }
    __syncthreads();
    if (tid < d1 * d2) {
        int m1 = tid / d2 - j1;
        int m2 = tid % d2 - j2;
        int m3 = m1 + m2;
        if (m3 >= -j3 && m3 <= j3) {
            int vmin = -j1 + j2 + m3;
            if (-j1 + m1 > vmin) vmin = -j1 + m1;
            if (vmin < 0) vmin = 0;
            int vmax = j2 + j3 + m1;
            if (j3 - j1 + j2 < vmax) vmax = j3 - j1 + j2;
            if (j3 + m3 < vmax) vmax = j3 + m3;
            double c = sqrt((double)(2 * j3 + 1) * dfact(j3 + j1 - j2) * dfact(j3 - j1 + j2) *
                            dfact(j1 + j2 - j3) * dfact(j3 + m3) * dfact(j3 - m3) /
                            (dfact(j1 + j2 + j3 + 1) * dfact(j1 - m1) * dfact(j1 + m1) *
                             dfact(j2 - m2) * dfact(j2 + m2)));
            double s = 0.0;
            for (int v = vmin; v <= vmax; v++) {
                double term = dfact(j2 + j3 + m1 - v) * dfact(j1 - m1 + v) /
                              (dfact(v) * dfact(j3 - j1 + j2 - v) * dfact(j3 + m3 - v) *
                               dfact(v + j1 - j2 - m3));
                if ((v + j2 + m2) & 1) term = -term;
                s += term;
            }
            Cs[((m1 + j1) * d2 + (m2 + j2)) * d3 + (m3 + j3)] = c * s;
        }
    }
    __syncthreads();
    int nel = d1 * d2 * d3;
    if (tid < nel) {
        int jj = tid / (d2 * d3);
        int ll = (tid / d3) % d2;
        int mm = tid % d3;
        double ar = 0.0;
        for (int i = 0; i < d1; i++)
            for (int k = 0; k < d2; k++)
                for (int n = 0; n < d3; n++) {
                    double cv = Cs[(i * d2 + k) * d3 + n];
                    if (cv == 0.0) continue;
                    double p1r = Q1r[i * d1 + jj], p1i = Q1i[i * d1 + jj];
                    double p2r = Q2r[k * d2 + ll], p2i = Q2i[k * d2 + ll];
                    double p3r = Q3r[n * d3 + mm], p3i = -Q3i[n * d3 + mm];
                    double t1r = p1r * p2r - p1i * p2i;
                    double t1i = p1r * p2i + p1i * p2r;
                    double t2r = t1r * p3r - t1i * p3i;
                    ar += t2r * cv;
                }
        outv[tid] = ar;
    }
    __syncthreads();
    if (tid == 0) {
        const double PWv[3] = {0.10206207261596575, 0.15309310892394862, 0.19764235376052370};
        double s = 0.0;
        for (int i = 0; i < nel; i++) s += outv[i] * outv[i];
        scale_s = PWv[j3] / sqrt(s);
    }
    __syncthreads();
    if (tid < nel) g_w3j[t * 125 + tid] = (float)(outv[tid] * scale_s);
}

// ======================= W2 relayout into tf32 B-fragment order =======================
// src: W2[c][col], col = ins*1024 + u*32 + w  (row-major [64,11264]); scaled by 1/8, tf32-rounded.
// dst float index: ((((ins*32+u)*4 + wtile)*4 + ks2)*32 + lane)*4 + parity*2 + bslot
//   where wtile=w>>3, n=w&7, ks=c>>3, kl=c&7, ks2=ks>>1, parity=ks&1,
//         lane=(n<<2)|(kl&3), bslot=kl>>2.
// Fragment semantics (m16n8k8 row.col): b0 = B[k=tig][n=g], b1 = B[k=tig+4][n=g].
__global__ void w2p_kernel(const float* __restrict__ W2) {
    int idx = blockIdx.x * 256 + threadIdx.x;
    if (idx >= 64 * 11264) return;
    int c = idx / 11264;
    int col = idx - c * 11264;
    int ins = col >> 10;
    int rem = col & 1023;
    int u = rem >> 5;
    int w = rem & 31;
    int wtile = w >> 3, n = w & 7;
    int ks = c >> 3, kl = c & 7;
    int ks2 = ks >> 1, par = ks & 1;
    int lane = (n << 2) | (kl & 3);
    int bslot = kl >> 2;
    int fidx = ((((ins * 32 + u) * 4 + wtile) * 4 + ks2) * 32 + lane) * 4 + par * 2 + bslot;
    ((float*)g_W2P)[fidx] = to_tf32(W2[idx] * 0.125f);
}

// ======================= weight-NN hidden layer (tf32-rounded output) =======================
__global__ void h_kernel(const float* __restrict__ radial, const float* __restrict__ W1,
                         float cst, int E) {
    __shared__ float rs[4][64];
    int le = threadIdx.x >> 6, c = threadIdx.x & 63;
    int e = blockIdx.x * 4 + le;
    rs[le][c] = (e < E) ? radial[e * 64 + c] : 0.f;
    __syncthreads();
    float a = 0.f;
#pragma unroll
    for (int r = 0; r < 64; r++) a += rs[le][r] * W1[r * 64 + c];
    a *= 0.125f;  // 1/sqrt(64)
    float hv = cst * a / (1.f + expf(-a));
    if (e < E) g_H[e * 64 + c] = to_tf32(hv);
}

// ======================= self-connection (writes d_out, clears poison) =======================
__global__ void sc_kernel(const float* __restrict__ nf, const float* __restrict__ w0,
                          const float* __restrict__ w1, const float* __restrict__ w2,
                          float* __restrict__ out) {
    __shared__ float xrow[288];
    int n = blockIdx.x;
    int t = threadIdx.x;
    xrow[t] = nf[n * 288 + t];
    __syncthreads();
    int O, d, wch, k;
    const float* W;
    if (t < 32)       { O = 0;   d = 1; wch = t;          k = 0;            W = w0; }
    else if (t < 128) { int r = t - 32;  O = 32;  d = 3; wch = r / 3; k = r - wch * 3; W = w1; }
    else              { int r = t - 128; O = 128; d = 5; wch = r / 5; k = r - wch * 5; W = w2; }
    float a = 0.f;
#pragma unroll
    for (int u = 0; u < 32; u++) a += xrow[O + u * d + k] * W[u * 32 + wch];
    out[n * 288 + t] = a * 0.17677669529663687f;  // 1/sqrt(32)
}

// ======================= fused message kernel (tf32 MMA) =======================
// Block = 256 threads = 8 warps, 32 edges.
// Warp (half = wid>>2, wtile = wid&3): 16-edge half x 8 w-columns.
// Thread lane: g = lane>>2, tig = lane&3. Rows er0 = half*16+g, er1 = er0+8.
// Cols wc0 = wtile*8 + 2*tig, wc1 = wc0+1.
// acc[p][9]: p0:(er0,wc0) p1:(er0,wc1) p2:(er1,wc0) p3:(er1,wc1).
template <int D1, int D2, int D3, int SO2, int O1, int KO, int W3OFF, int PB4>
__device__ __forceinline__ void process_ins(float* __restrict__ xs,
                                            float* __restrict__ zs, float* __restrict__ ss,
                                            const float* __restrict__ shT,
                                            const float (&af)[8][4], float (&acc)[4][9],
                                            int tid, int lane, int wtile,
                                            int er0, int er1) {
    __syncthreads();  // protect ss/zs reuse
    // s[e,i,k] = sum_j w3j[i,j,k] * sh[e,j]
    for (int idx = tid; idx < 32 * D1 * D3; idx += NTHR) {
        int e = idx & 31;
        int r = idx >> 5;
        int i = r / D3;
        int k = r - i * D3;
        float a = 0.f;
#pragma unroll
        for (int j = 0; j < D2; j++)
            a += g_w3j[W3OFF + (i * D2 + j) * D3 + k] * shT[(SO2 + j) * 33 + e];
        ss[(i * D3 + k) * 33 + e] = a;
    }
    __syncthreads();
    // z[e,u,k] = sum_i x[e,u,i] * s[e,i,k]
    for (int idx = tid; idx < 1024; idx += NTHR) {
        int e = idx & 31;
        int u = idx >> 5;
        float xv[D1];
#pragma unroll
        for (int i = 0; i < D1; i++) xv[i] = xs[(O1 + u * D1 + i) * 33 + e];
#pragma unroll
        for (int k = 0; k < D3; k++) {
            float z = 0.f;
#pragma unroll
            for (int i = 0; i < D1; i++) z += xv[i] * ss[(i * D3 + k) * 33 + e];
            zs[(u * D3 + k) * 33 + e] = z;
        }
    }
    __syncthreads();
    // MMA: wv fragment per u, consumed immediately against z.
    const float4* __restrict__ Bp = g_W2P + PB4 + wtile * 128 + lane;
#pragma unroll 1
    for (int u = 0; u < 32; u++) {
        const float4* __restrict__ Bu = Bp + u * 512;
        float4 B0 = __ldg(Bu);
        float4 B1 = __ldg(Bu + 32);
        float4 B2 = __ldg(Bu + 64);
        float4 B3 = __ldg(Bu + 96);
        float c0[4] = {0.f, 0.f, 0.f, 0.f};
        float c1[4] = {0.f, 0.f, 0.f, 0.f};
        mma_tf32(c0, af[0], B0.x, B0.y);
        mma_tf32(c1, af[1], B0.z, B0.w);
        mma_tf32(c0, af[2], B1.x, B1.y);
        mma_tf32(c1, af[3], B1.z, B1.w);
        mma_tf32(c0, af[4], B2.x, B2.y);
        mma_tf32(c1, af[5], B2.z, B2.w);
        mma_tf32(c0, af[6], B3.x, B3.y);
        mma_tf32(c1, af[7], B3.z, B3.w);
        float wv0 = c0[0] + c1[0];
        float wv1 = c0[1] + c1[1];
        float wv2 = c0[2] + c1[2];
        float wv3 = c0[3] + c1[3];
#pragma unroll
        for (int k = 0; k < D3; k++) {
            float z0 = zs[(u * D3 + k) * 33 + er0];
            float z1 = zs[(u * D3 + k) * 33 + er1];
            acc[0][KO + k] += wv0 * z0;
            acc[1][KO + k] += wv1 * z0;
            acc[2][KO + k] += wv2 * z1;
            acc[3][KO + k] += wv3 * z1;
        }
    }
}

#define PINS(IDX, A, B, Cc)                                                                   \
    process_ins<DIMS_[A], DIMS_[B], DIMS_[Cc], SO_[B], OFF_[A], KO_[Cc], IDX * 125,           \
                IDX * 16384>(xs, zs, ss, shT, af, acc, tid, lane, wtile, er0, er1)

__global__ void __launch_bounds__(NTHR, 2)
msg_kernel(const float* __restrict__ nf, const int* __restrict__ ei,
           const float* __restrict__ shg, float* __restrict__ out, int E) {
    extern __shared__ float smem[];
    float* xs  = smem;            // 288*33 = 9504 (transposed, padded)
    float* hs  = xs + 9504;       // 32*64  = 2048
    float* zs  = hs + 2048;       // 32*5*33 = 5280
    float* ss  = zs + 5280;       // 25*33 = 825
    float* shT = ss + 825;        // 9*33 = 297
    int* srcdst = (int*)(shT + 297);  // 64 ints: [0:32)=src, [32:64)=dst
    int tid = threadIdx.x;
    int e0 = blockIdx.x * 32;

    if (tid < 64) {
        int e = e0 + (tid & 31);
        int which = tid >> 5;
        srcdst[tid] = (e < E) ? ei[which * E + e] : 0;
    }
    __syncthreads();
    for (int idx = tid; idx < 32 * 288; idx += NTHR) {
        int e = idx / 288;
        int c = idx - e * 288;
        xs[c * 33 + e] = (e0 + e < E) ? nf[srcdst[e] * 288 + c] : 0.f;
    }
    for (int idx = tid; idx < 32 * 64; idx += NTHR) {
        int e = idx >> 6;
        int c = idx & 63;
        hs[e * 64 + c] = (e0 + e < E) ? g_H[(e0 + e) * 64 + c] : 0.f;
    }
    for (int idx = tid; idx < 32 * 9; idx += NTHR) {
        int e = idx & 31;
        int j = idx >> 5;
        shT[j * 33 + e] = (e0 + e < E) ? shg[(e0 + e) * 9 + j] : 0.f;
    }
    __syncthreads();  // hs ready for A-fragment build

    int lane = tid & 31;
    int wid = tid >> 5;
    int half = wid >> 2, wtile = wid & 3;
    int g = lane >> 2, tig = lane & 3;
    int er0 = half * 16 + g, er1 = er0 + 8;
    int wc0 = wtile * 8 + 2 * tig, wc1 = wc0 + 1;

    // A fragments (h, tf32) live in registers for the whole kernel.
    float af[8][4];
#pragma unroll
    for (int ks = 0; ks < 8; ks++) {
        af[ks][0] = hs[er0 * 64 + ks * 8 + tig];
        af[ks][1] = hs[er1 * 64 + ks * 8 + tig];
        af[ks][2] = hs[er0 * 64 + ks * 8 + tig + 4];
        af[ks][3] = hs[er1 * 64 + ks * 8 + tig + 4];
    }

    float acc[4][9];
#pragma unroll
    for (int p = 0; p < 4; p++)
#pragma unroll
        for (int k = 0; k < 9; k++) acc[p][k] = 0.f;

    PINS(0, 0, 0, 0); PINS(1, 0, 1, 1); PINS(2, 0, 2, 2); PINS(3, 1, 0, 1);
    PINS(4, 1, 1, 0); PINS(5, 1, 1, 2); PINS(6, 1, 2, 1); PINS(7, 2, 0, 2);
    PINS(8, 2, 1, 1); PINS(9, 2, 2, 0); PINS(10, 2, 2, 2);

    const float inv = 0.31622776601683794f;  // 1/sqrt(NUM_NEIGHBORS)
#pragma unroll
    for (int p = 0; p < 4; p++) {
        int e = (p & 2) ? er1 : er0;
        int wcol = (p & 1) ? wc1 : wc0;
        if (e0 + e >= E) continue;
        int node = srcdst[32 + e];
        float* op = out + node * 288;
        atomicAdd(op + wcol, inv * acc[p][0]);
#pragma unroll
        for (int k = 0; k < 3; k++) atomicAdd(op + 32 + wcol * 3 + k, inv * acc[p][1 + k]);
#pragma unroll
        for (int k = 0; k < 5; k++) atomicAdd(op + 128 + wcol * 5 + k, inv * acc[p][4 + k]);
    }
}

// ======================= host: numpy RandomState(0) SILU_CST reproduction =======================
namespace {
struct NpRng {
    uint32_t mt[624];
    int mti;
    bool has_g;
    double g;
};
inline void rng_seed(NpRng& s, uint32_t sd) {
    s.mt[0] = sd;
    for (int i = 1; i < 624; i++)
        s.mt[i] = 1812433253u * (s.mt[i - 1] ^ (s.mt[i - 1] >> 30)) + (uint32_t)i;
    s.mti = 624;
    s.has_g = false;
    s.g = 0.0;
}
inline uint32_t rng_u32(NpRng& s) {
    if (s.mti >= 624) {
        for (int i = 0; i < 624; i++) {
            uint32_t y = (s.mt[i] & 0x80000000u) | (s.mt[(i + 1) % 624] & 0x7fffffffu);
            s.mt[i] = s.mt[(i + 397) % 624] ^ (y >> 1) ^ ((y & 1u) ? 0x9908b0dfu : 0u);
        }
        s.mti = 0;
    }
    uint32_t y = s.mt[s.mti++];
    y ^= y >> 11;
    y ^= (y << 7) & 0x9d2c5680u;
    y ^= (y << 15) & 0xefc60000u;
    y ^= y >> 18;
    return y;
}
inline double rng_double(NpRng& s) {
    uint32_t a = rng_u32(s) >> 5;
    uint32_t b = rng_u32(s) >> 6;
    return ((double)a * 67108864.0 + (double)b) / 9007199254740992.0;
}
inline double rng_gauss(NpRng& s) {
    if (s.has_g) {
        s.has_g = false;
        return s.g;
    }
    double x1, x2, r2;
    do {
        x1 = 2.0 * rng_double(s) - 1.0;
        x2 = 2.0 * rng_double(s) - 1.0;
        r2 = x1 * x1 + x2 * x2;
    } while (r2 >= 1.0 || r2 == 0.0);
    double f = sqrt(-2.0 * log(r2) / r2);
    s.g = f * x1;
    s.has_g = true;
    return f * x2;
}
inline double compute_silu_cst() {
    NpRng s;
    rng_seed(s, 0u);
    double sum = 0.0;
    for (int i = 0; i < 1000000; i++) {
        double z = rng_gauss(s);
        double sl = z / (1.0 + exp(-z));
        sum += sl * sl;
    }
    return 1.0 / sqrt(sum / 1000000.0);
}
}  // namespace

// ======================= launch =======================
extern "C" void kernel_launch(void* const* d_in, const int* in_sizes, int n_in,
                              void* d_out, int out_size) {
    const float* nf     = (const float*)d_in[0];
    const int*   ei     = (const int*)d_in[1];
    const float* sh     = (const float*)d_in[2];
    const float* radial = (const float*)d_in[3];
    const float* W1     = (const float*)d_in[4];
    const float* W2     = (const float*)d_in[5];
    const float* Wsc0   = (const float*)d_in[6];
    const float* Wsc1   = (const float*)d_in[7];
    const float* Wsc2   = (const float*)d_in[8];
    float* out = (float*)d_out;
    int N = in_sizes[0] / 288;
    int E = in_sizes[1] / 2;

    float cst = (float)compute_silu_cst();

    const size_t SMEM = (9504 + 2048 + 5280 + 825 + 297) * 4 + 64 * 4;  // 72072 B
    cudaFuncSetAttribute(msg_kernel, cudaFuncAttributeMaxDynamicSharedMemorySize, (int)SMEM);

    w3j_setup_kernel<<<11, 128>>>();
    w2p_kernel<<<(64 * 11264 + 255) / 256, 256>>>(W2);
    h_kernel<<<(E + 3) / 4, 256>>>(radial, W1, cst, E);
    sc_kernel<<<N, 288>>>(nf, Wsc0, Wsc1, Wsc2, out);
    msg_kernel<<<(E + 31) / 32, NTHR, SMEM>>>(nf, ei, sh, out, E);
}

// round 6
// speedup vs baseline: 10.5500x; 1.0097x over previous
#include <cuda_runtime.h>
#include <math.h>
#include <stdint.h>

#define NTHR 256
#define TEDGE 64
#define EPAD 65

// ---------------- device scratch (static, no allocation) ----------------
__device__ float g_w3j[11 * 125];        // per-instruction wigner3j, pre-scaled by PW[l3]
__device__ float4 g_W2P[11 * 32 * 4 * 4 * 32];  // W2 in tf32 B-fragment layout (2.88 MB)
__device__ float g_H[20000 * 64];        // weight-NN hidden activations (tf32-rounded)

// irrep constants
constexpr int DIMS_[3] = {1, 3, 5};
constexpr int OFF_[3]  = {0, 32, 128};  // offsets into 288-dim feature
constexpr int SO_[3]   = {0, 1, 4};     // offsets into 9-dim sh
constexpr int KO_[3]   = {0, 1, 4};     // offsets into 9-slot accumulator

__device__ __forceinline__ float to_tf32(float v) {
    uint32_t r;
    asm("cvt.rna.tf32.f32 %0, %1;" : "=r"(r) : "f"(v));
    return __uint_as_float(r);
}

// tf32 m16n8k8 MMA, D += A*B
__device__ __forceinline__ void mma_tf32(float* d, const float* a, float b0, float b1) {
    asm volatile(
        "mma.sync.aligned.m16n8k8.row.col.f32.tf32.tf32.f32 "
        "{%0,%1,%2,%3}, {%4,%5,%6,%7}, {%8,%9}, {%0,%1,%2,%3};\n"
        : "+f"(d[0]), "+f"(d[1]), "+f"(d[2]), "+f"(d[3])
        : "r"(__float_as_uint(a[0])), "r"(__float_as_uint(a[1])),
          "r"(__float_as_uint(a[2])), "r"(__float_as_uint(a[3])),
          "r"(__float_as_uint(b0)), "r"(__float_as_uint(b1)));
}

// ======================= wigner-3j setup (reference algorithm) =======================
__device__ __forceinline__ double dfact(int n) {
    double r = 1.0;
    for (int i = 2; i <= n; i++) r *= (double)i;
    return r;
}

__device__ void build_q(int l, double* qr, double* qi) {
    int D = 2 * l + 1;
    for (int i = 0; i < D * D; i++) { qr[i] = 0.0; qi[i] = 0.0; }
    const double s2 = 0.70710678118654752440;
    for (int m = -l; m < 0; m++) {
        qr[(l + m) * D + (l - m)] = s2;
        qi[(l + m) * D + (l + m)] = -s2;
    }
    qr[l * D + l] = 1.0;
    for (int m = 1; m <= l; m++) {
        double sg = (m & 1) ? -1.0 : 1.0;
        qr[(l + m) * D + (l + m)] = sg * s2;
        qi[(l + m) * D + (l - m)] = sg * s2;
    }
    double fr, fi;
    switch (l & 3) {
        case 0: fr = 1;  fi = 0;  break;
        case 1: fr = 0;  fi = -1; break;
        case 2: fr = -1; fi = 0;  break;
        default: fr = 0; fi = 1;  break;
    }
    for (int i = 0; i < D * D; i++) {
        double r = qr[i], im = qi[i];
        qr[i] = r * fr - im * fi;
        qi[i] = r * fi + im * fr;
    }
}

__global__ void w3j_setup_kernel() {
    const int L1[11] = {0, 0, 0, 1, 1, 1, 1, 2, 2, 2, 2};
    const int L2[11] = {0, 1, 2, 0, 1, 1, 2, 0, 1, 2, 2};
    const int L3[11] = {0, 1, 2, 1, 0, 2, 1, 2, 1, 0, 2};
    int t = blockIdx.x;
    int j1 = L1[t], j2 = L2[t], j3 = L3[t];
    int d1 = 2 * j1 + 1, d2 = 2 * j2 + 1, d3 = 2 * j3 + 1;
    __shared__ double Cs[125];
    __shared__ double Q1r[25], Q1i[25], Q2r[25], Q2i[25], Q3r[25], Q3i[25];
    __shared__ double outv[125];
    __shared__ double scale_s;
    int tid = threadIdx.x;
    if (tid < 125) Cs[tid] = 0.0;
    if (tid == 0) {
        build_q(j1, Q1r, Q1i);
        build_q(j2, Q2r, Q2i);
        build_q(j3, Q3r, Q3i);
    }
    __syncthreads();
    if (tid < d1 * d2) {
        int m1 = tid / d2 - j1;
        int m2 = tid % d2 - j2;
        int m3 = m1 + m2;
        if (m3 >= -j3 && m3 <= j3) {
            int vmin = -j1 + j2 + m3;
            if (-j1 + m1 > vmin) vmin = -j1 + m1;
            if (vmin < 0) vmin = 0;
            int vmax = j2 + j3 + m1;
            if (j3 - j1 + j2 < vmax) vmax = j3 - j1 + j2;
            if (j3 + m3 < vmax) vmax = j3 + m3;
            double c = sqrt((double)(2 * j3 + 1) * dfact(j3 + j1 - j2) * dfact(j3 - j1 + j2) *
                            dfact(j1 + j2 - j3) * dfact(j3 + m3) * dfact(j3 - m3) /
                            (dfact(j1 + j2 + j3 + 1) * dfact(j1 - m1) * dfact(j1 + m1) *
                             dfact(j2 - m2) * dfact(j2 + m2)));
            double s = 0.0;
            for (int v = vmin; v <= vmax; v++) {
                double term = dfact(j2 + j3 + m1 - v) * dfact(j1 - m1 + v) /
                              (dfact(v) * dfact(j3 - j1 + j2 - v) * dfact(j3 + m3 - v) *
                               dfact(v + j1 - j2 - m3));
                if ((v + j2 + m2) & 1) term = -term;
                s += term;
            }
            Cs[((m1 + j1) * d2 + (m2 + j2)) * d3 + (m3 + j3)] = c * s;
        }
    }
    __syncthreads();
    int nel = d1 * d2 * d3;
    if (tid < nel) {
        int jj = tid / (d2 * d3);
        int ll = (tid / d3) % d2;
        int mm = tid % d3;
        double ar = 0.0;
        for (int i = 0; i < d1; i++)
            for (int k = 0; k < d2; k++)
                for (int n = 0; n < d3; n++) {
                    double cv = Cs[(i * d2 + k) * d3 + n];
                    if (cv == 0.0) continue;
                    double p1r = Q1r[i * d1 + jj], p1i = Q1i[i * d1 + jj];
                    double p2r = Q2r[k * d2 + ll], p2i = Q2i[k * d2 + ll];
                    double p3r = Q3r[n * d3 + mm], p3i = -Q3i[n * d3 + mm];
                    double t1r = p1r * p2r - p1i * p2i;
                    double t1i = p1r * p2i + p1i * p2r;
                    double t2r = t1r * p3r - t1i * p3i;
                    ar += t2r * cv;
                }
        outv[tid] = ar;
    }
    __syncthreads();
    if (tid == 0) {
        const double PWv[3] = {0.10206207261596575, 0.15309310892394862, 0.19764235376052370};
        double s = 0.0;
        for (int i = 0; i < nel; i++) s += outv[i] * outv[i];
        scale_s = PWv[j3] / sqrt(s);
    }
    __syncthreads();
    if (tid < nel) g_w3j[t * 125 + tid] = (float)(outv[tid] * scale_s);
}

// ======================= W2 relayout into tf32 B-fragment order =======================
// src: W2[c][col], col = ins*1024 + u*32 + w  (row-major [64,11264]); scaled by 1/8, tf32-rounded.
// dst float index: ((((ins*32+u)*4 + wtile)*4 + ks2)*32 + lane)*4 + parity*2 + bslot
__global__ void w2p_kernel(const float* __restrict__ W2) {
    int idx = blockIdx.x * 256 + threadIdx.x;
    if (idx >= 64 * 11264) return;
    int c = idx / 11264;
    int col = idx - c * 11264;
    int ins = col >> 10;
    int rem = col & 1023;
    int u = rem >> 5;
    int w = rem & 31;
    int wtile = w >> 3, n = w & 7;
    int ks = c >> 3, kl = c & 7;
    int ks2 = ks >> 1, par = ks & 1;
    int lane = (n << 2) | (kl & 3);
    int bslot = kl >> 2;
    int fidx = ((((ins * 32 + u) * 4 + wtile) * 4 + ks2) * 32 + lane) * 4 + par * 2 + bslot;
    ((float*)g_W2P)[fidx] = to_tf32(W2[idx] * 0.125f);
}

// ======================= weight-NN hidden layer (tf32-rounded output) =======================
__global__ void h_kernel(const float* __restrict__ radial, const float* __restrict__ W1,
                         float cst, int E) {
    __shared__ float rs[4][64];
    int le = threadIdx.x >> 6, c = threadIdx.x & 63;
    int e = blockIdx.x * 4 + le;
    rs[le][c] = (e < E) ? radial[e * 64 + c] : 0.f;
    __syncthreads();
    float a = 0.f;
#pragma unroll
    for (int r = 0; r < 64; r++) a += rs[le][r] * W1[r * 64 + c];
    a *= 0.125f;  // 1/sqrt(64)
    float hv = cst * a / (1.f + expf(-a));
    if (e < E) g_H[e * 64 + c] = to_tf32(hv);
}

// ======================= self-connection (writes d_out, clears poison) =======================
__global__ void sc_kernel(const float* __restrict__ nf, const float* __restrict__ w0,
                          const float* __restrict__ w1, const float* __restrict__ w2,
                          float* __restrict__ out) {
    __shared__ float xrow[288];
    int n = blockIdx.x;
    int t = threadIdx.x;
    xrow[t] = nf[n * 288 + t];
    __syncthreads();
    int O, d, wch, k;
    const float* W;
    if (t < 32)       { O = 0;   d = 1; wch = t;          k = 0;            W = w0; }
    else if (t < 128) { int r = t - 32;  O = 32;  d = 3; wch = r / 3; k = r - wch * 3; W = w1; }
    else              { int r = t - 128; O = 128; d = 5; wch = r / 5; k = r - wch * 5; W = w2; }
    float a = 0.f;
#pragma unroll
    for (int u = 0; u < 32; u++) a += xrow[O + u * d + k] * W[u * 32 + wch];
    out[n * 288 + t] = a * 0.17677669529663687f;  // 1/sqrt(32)
}

// ======================= fused message kernel (tf32 MMA, 64-edge tiles) =======================
// Block = 256 threads = 8 warps, 64 edges.
// Warp wid: wtile = wid&3, half = wid>>2. Warp owns row-tiles {2*half, 2*half+1}
// (edges [32*half, 32*half+32)), and w-columns [wtile*8, wtile*8+8).
// Thread lane: g = lane>>2, tig = lane&3. Row-tile t rows: ert = t*16+g, ert+8.
// Cols wc0 = wtile*8 + 2*tig, wc1 = wc0+1.
// acc[t*4+p][9]: p0:(ert,wc0) p1:(ert,wc1) p2:(ert+8,wc0) p3:(ert+8,wc1).
template <int D1, int D2, int D3, int SO2, int O1, int KO, int W3OFF, int PB4>
__device__ __forceinline__ void process_ins(float* __restrict__ xs,
                                            float* __restrict__ zs, float* __restrict__ ss,
                                            const float* __restrict__ shT,
                                            const float (&af)[2][8][4], float (&acc)[8][9],
                                            int tid, int lane, int wtile,
                                            const int (&ert)[2]) {
    // B prefetch for u=0 (no smem dependency — issue before the barrier)
    const float4* __restrict__ Bp = g_W2P + PB4 + wtile * 128 + lane;
    float4 Bc[4], Bn[4];
#pragma unroll
    for (int j = 0; j < 4; j++) Bc[j] = __ldg(Bp + j * 32);

    __syncthreads();  // protect ss/zs reuse
    // s[e,i,k] = sum_j w3j[i,j,k] * sh[e,j]
    for (int idx = tid; idx < TEDGE * D1 * D3; idx += NTHR) {
        int e = idx & (TEDGE - 1);
        int r = idx >> 6;
        int i = r / D3;
        int k = r - i * D3;
        float a = 0.f;
#pragma unroll
        for (int j = 0; j < D2; j++)
            a += g_w3j[W3OFF + (i * D2 + j) * D3 + k] * shT[(SO2 + j) * EPAD + e];
        ss[(i * D3 + k) * EPAD + e] = a;
    }
    __syncthreads();
    // z[e,u,k] = sum_i x[e,u,i] * s[e,i,k]
    for (int idx = tid; idx < TEDGE * 32; idx += NTHR) {
        int e = idx & (TEDGE - 1);
        int u = idx >> 6;
        float xv[D1];
#pragma unroll
        for (int i = 0; i < D1; i++) xv[i] = xs[(O1 + u * D1 + i) * EPAD + e];
#pragma unroll
        for (int k = 0; k < D3; k++) {
            float z = 0.f;
#pragma unroll
            for (int i = 0; i < D1; i++) z += xv[i] * ss[(i * D3 + k) * EPAD + e];
            zs[(u * D3 + k) * EPAD + e] = z;
        }
    }
    __syncthreads();
    // MMA: wv fragment per u (shared across both row-tiles), consumed immediately against z.
#pragma unroll 1
    for (int u = 0; u < 32; u++) {
        if (u < 31) {
            const float4* __restrict__ Bu = Bp + (u + 1) * 512;
            Bn[0] = __ldg(Bu);
            Bn[1] = __ldg(Bu + 32);
            Bn[2] = __ldg(Bu + 64);
            Bn[3] = __ldg(Bu + 96);
        }
#pragma unroll
        for (int t = 0; t < 2; t++) {
            float c0[4] = {0.f, 0.f, 0.f, 0.f};
            float c1[4] = {0.f, 0.f, 0.f, 0.f};
            mma_tf32(c0, af[t][0], Bc[0].x, Bc[0].y);
            mma_tf32(c1, af[t][1], Bc[0].z, Bc[0].w);
            mma_tf32(c0, af[t][2], Bc[1].x, Bc[1].y);
            mma_tf32(c1, af[t][3], Bc[1].z, Bc[1].w);
            mma_tf32(c0, af[t][4], Bc[2].x, Bc[2].y);
            mma_tf32(c1, af[t][5], Bc[2].z, Bc[2].w);
            mma_tf32(c0, af[t][6], Bc[3].x, Bc[3].y);
            mma_tf32(c1, af[t][7], Bc[3].z, Bc[3].w);
            float wv0 = c0[0] + c1[0];
            float wv1 = c0[1] + c1[1];
            float wv2 = c0[2] + c1[2];
            float wv3 = c0[3] + c1[3];
            int er0 = ert[t], er1 = ert[t] + 8;
#pragma unroll
            for (int k = 0; k < D3; k++) {
                float z0 = zs[(u * D3 + k) * EPAD + er0];
                float z1 = zs[(u * D3 + k) * EPAD + er1];
                acc[t * 4 + 0][KO + k] += wv0 * z0;
                acc[t * 4 + 1][KO + k] += wv1 * z0;
                acc[t * 4 + 2][KO + k] += wv2 * z1;
                acc[t * 4 + 3][KO + k] += wv3 * z1;
            }
        }
#pragma unroll
        for (int j = 0; j < 4; j++) Bc[j] = Bn[j];
    }
}

#define PINS(IDX, A, B, Cc)                                                                   \
    process_ins<DIMS_[A], DIMS_[B], DIMS_[Cc], SO_[B], OFF_[A], KO_[Cc], IDX * 125,           \
                IDX * 16384>(xs, zs, ss, shT, af, acc, tid, lane, wtile, ert)

__global__ void __launch_bounds__(NTHR, 1)
msg_kernel(const float* __restrict__ nf, const int* __restrict__ ei,
           const float* __restrict__ shg, float* __restrict__ out, int E) {
    extern __shared__ float smem[];
    float* xs  = smem;                 // 288*65 = 18720 (transposed, padded)
    float* hs  = xs + 288 * EPAD;      // 64*64  = 4096
    float* zs  = hs + TEDGE * 64;      // 32*5*65 = 10400
    float* ss  = zs + 32 * 5 * EPAD;   // 25*65 = 1625
    float* shT = ss + 25 * EPAD;       // 9*65 = 585
    int* srcdst = (int*)(shT + 9 * EPAD);  // 128 ints: [0:64)=src, [64:128)=dst
    int tid = threadIdx.x;
    int e0 = blockIdx.x * TEDGE;

    if (tid < 128) {
        int e = e0 + (tid & 63);
        int which = tid >> 6;
        srcdst[tid] = (e < E) ? ei[which * E + e] : 0;
    }
    __syncthreads();
    for (int idx = tid; idx < TEDGE * 288; idx += NTHR) {
        int e = idx / 288;
        int c = idx - e * 288;
        xs[c * EPAD + e] = (e0 + e < E) ? nf[srcdst[e] * 288 + c] : 0.f;
    }
    for (int idx = tid; idx < TEDGE * 64; idx += NTHR) {
        int e = idx >> 6;
        int c = idx & 63;
        hs[e * 64 + c] = (e0 + e < E) ? g_H[(e0 + e) * 64 + c] : 0.f;
    }
    for (int idx = tid; idx < TEDGE * 9; idx += NTHR) {
        int e = idx & 63;
        int j = idx >> 6;
        shT[j * EPAD + e] = (e0 + e < E) ? shg[(e0 + e) * 9 + j] : 0.f;
    }
    __syncthreads();  // hs ready for A-fragment build

    int lane = tid & 31;
    int wid = tid >> 5;
    int half = wid >> 2, wtile = wid & 3;
    int g = lane >> 2, tig = lane & 3;
    int ert[2] = {(2 * half) * 16 + g, (2 * half + 1) * 16 + g};
    int wc0 = wtile * 8 + 2 * tig, wc1 = wc0 + 1;

    // A fragments (h, tf32) for both row-tiles live in registers for the whole kernel.
    float af[2][8][4];
#pragma unroll
    for (int t = 0; t < 2; t++)
#pragma unroll
        for (int ks = 0; ks < 8; ks++) {
            af[t][ks][0] = hs[ert[t] * 64 + ks * 8 + tig];
            af[t][ks][1] = hs[(ert[t] + 8) * 64 + ks * 8 + tig];
            af[t][ks][2] = hs[ert[t] * 64 + ks * 8 + tig + 4];
            af[t][ks][3] = hs[(ert[t] + 8) * 64 + ks * 8 + tig + 4];
        }

    float acc[8][9];
#pragma unroll
    for (int p = 0; p < 8; p++)
#pragma unroll
        for (int k = 0; k < 9; k++) acc[p][k] = 0.f;

    PINS(0, 0, 0, 0); PINS(1, 0, 1, 1); PINS(2, 0, 2, 2); PINS(3, 1, 0, 1);
    PINS(4, 1, 1, 0); PINS(5, 1, 1, 2); PINS(6, 1, 2, 1); PINS(7, 2, 0, 2);
    PINS(8, 2, 1, 1); PINS(9, 2, 2, 0); PINS(10, 2, 2, 2);

    const float inv = 0.31622776601683794f;  // 1/sqrt(NUM_NEIGHBORS)
#pragma unroll
    for (int t = 0; t < 2; t++) {
#pragma unroll
        for (int p = 0; p < 4; p++) {
            int e = ert[t] + ((p & 2) ? 8 : 0);
            int wcol = (p & 1) ? wc1 : wc0;
            if (e0 + e >= E) continue;
            int node = srcdst[64 + e];
            float* op = out + node * 288;
            float* ac = acc[t * 4 + p];
            atomicAdd(op + wcol, inv * ac[0]);
#pragma unroll
            for (int k = 0; k < 3; k++) atomicAdd(op + 32 + wcol * 3 + k, inv * ac[1 + k]);
#pragma unroll
            for (int k = 0; k < 5; k++) atomicAdd(op + 128 + wcol * 5 + k, inv * ac[4 + k]);
        }
    }
}

// ======================= host: numpy RandomState(0) SILU_CST reproduction =======================
namespace {
struct NpRng {
    uint32_t mt[624];
    int mti;
    bool has_g;
    double g;
};
inline void rng_seed(NpRng& s, uint32_t sd) {
    s.mt[0] = sd;
    for (int i = 1; i < 624; i++)
        s.mt[i] = 1812433253u * (s.mt[i - 1] ^ (s.mt[i - 1] >> 30)) + (uint32_t)i;
    s.mti = 624;
    s.has_g = false;
    s.g = 0.0;
}
inline uint32_t rng_u32(NpRng& s) {
    if (s.mti >= 624) {
        for (int i = 0; i < 624; i++) {
            uint32_t y = (s.mt[i] & 0x80000000u) | (s.mt[(i + 1) % 624] & 0x7fffffffu);
            s.mt[i] = s.mt[(i + 397) % 624] ^ (y >> 1) ^ ((y & 1u) ? 0x9908b0dfu : 0u);
        }
        s.mti = 0;
    }
    uint32_t y = s.mt[s.mti++];
    y ^= y >> 11;
    y ^= (y << 7) & 0x9d2c5680u;
    y ^= (y << 15) & 0xefc60000u;
    y ^= y >> 18;
    return y;
}
inline double rng_double(NpRng& s) {
    uint32_t a = rng_u32(s) >> 5;
    uint32_t b = rng_u32(s) >> 6;
    return ((double)a * 67108864.0 + (double)b) / 9007199254740992.0;
}
inline double rng_gauss(NpRng& s) {
    if (s.has_g) {
        s.has_g = false;
        return s.g;
    }
    double x1, x2, r2;
    do {
        x1 = 2.0 * rng_double(s) - 1.0;
        x2 = 2.0 * rng_double(s) - 1.0;
        r2 = x1 * x1 + x2 * x2;
    } while (r2 >= 1.0 || r2 == 0.0);
    double f = sqrt(-2.0 * log(r2) / r2);
    s.g = f * x1;
    s.has_g = true;
    return f * x2;
}
inline double compute_silu_cst() {
    NpRng s;
    rng_seed(s, 0u);
    double sum = 0.0;
    for (int i = 0; i < 1000000; i++) {
        double z = rng_gauss(s);
        double sl = z / (1.0 + exp(-z));
        sum += sl * sl;
    }
    return 1.0 / sqrt(sum / 1000000.0);
}
}  // namespace

// ======================= launch =======================
extern "C" void kernel_launch(void* const* d_in, const int* in_sizes, int n_in,
                              void* d_out, int out_size) {
    const float* nf     = (const float*)d_in[0];
    const int*   ei     = (const int*)d_in[1];
    const float* sh     = (const float*)d_in[2];
    const float* radial = (const float*)d_in[3];
    const float* W1     = (const float*)d_in[4];
    const float* W2     = (const float*)d_in[5];
    const float* Wsc0   = (const float*)d_in[6];
    const float* Wsc1   = (const float*)d_in[7];
    const float* Wsc2   = (const float*)d_in[8];
    float* out = (float*)d_out;
    int N = in_sizes[0] / 288;
    int E = in_sizes[1] / 2;

    float cst = (float)compute_silu_cst();

    const size_t SMEM = (288 * EPAD + TEDGE * 64 + 32 * 5 * EPAD + 25 * EPAD + 9 * EPAD) * 4
                        + 128 * 4;  // ~142 KB
    cudaFuncSetAttribute(msg_kernel, cudaFuncAttributeMaxDynamicSharedMemorySize, (int)SMEM);

    w3j_setup_kernel<<<11, 128>>>();
    w2p_kernel<<<(64 * 11264 + 255) / 256, 256>>>(W2);
    h_kernel<<<(E + 3) / 4, 256>>>(radial, W1, cst, E);
    sc_kernel<<<N, 288>>>(nf, Wsc0, Wsc1, Wsc2, out);
    msg_kernel<<<(E + TEDGE - 1) / TEDGE, NTHR, SMEM>>>(nf, ei, sh, out, E);
}

// round 7
// speedup vs baseline: 11.2572x; 1.0670x over previous
#include <cuda_runtime.h>
#include <cuda_fp16.h>
#include <math.h>
#include <stdint.h>

#define NTHR 256
#define TEDGE 64
#define EPAD 65

// ---------------- device scratch (static, no allocation) ----------------
__device__ float g_w3j[11 * 125];        // per-instruction wigner3j, pre-scaled by PW[l3]
__device__ uint4 g_W2H[11 * 32 * 4 * 2 * 32];  // W2 in fp16 B-fragment layout (1.44 MB)
__device__ __half g_Hh[20000 * 64];      // weight-NN hidden activations (fp16)

// irrep constants
constexpr int DIMS_[3] = {1, 3, 5};
constexpr int OFF_[3]  = {0, 32, 128};  // offsets into 288-dim feature
constexpr int SO_[3]   = {0, 1, 4};     // offsets into 9-dim sh
constexpr int KO_[3]   = {0, 1, 4};     // offsets into 9-slot accumulator

// fp16 m16n8k16 MMA, D += A*B (fp32 accumulate)
__device__ __forceinline__ void mma_f16(float* d, const uint32_t* a, uint32_t b0, uint32_t b1) {
    asm volatile(
        "mma.sync.aligned.m16n8k16.row.col.f32.f16.f16.f32 "
        "{%0,%1,%2,%3}, {%4,%5,%6,%7}, {%8,%9}, {%0,%1,%2,%3};\n"
        : "+f"(d[0]), "+f"(d[1]), "+f"(d[2]), "+f"(d[3])
        : "r"(a[0]), "r"(a[1]), "r"(a[2]), "r"(a[3]), "r"(b0), "r"(b1));
}

// ======================= wigner-3j setup (reference algorithm) =======================
__device__ __forceinline__ double dfact(int n) {
    double r = 1.0;
    for (int i = 2; i <= n; i++) r *= (double)i;
    return r;
}

__device__ void build_q(int l, double* qr, double* qi) {
    int D = 2 * l + 1;
    for (int i = 0; i < D * D; i++) { qr[i] = 0.0; qi[i] = 0.0; }
    const double s2 = 0.70710678118654752440;
    for (int m = -l; m < 0; m++) {
        qr[(l + m) * D + (l - m)] = s2;
        qi[(l + m) * D + (l + m)] = -s2;
    }
    qr[l * D + l] = 1.0;
    for (int m = 1; m <= l; m++) {
        double sg = (m & 1) ? -1.0 : 1.0;
        qr[(l + m) * D + (l + m)] = sg * s2;
        qi[(l + m) * D + (l - m)] = sg * s2;
    }
    double fr, fi;
    switch (l & 3) {
        case 0: fr = 1;  fi = 0;  break;
        case 1: fr = 0;  fi = -1; break;
        case 2: fr = -1; fi = 0;  break;
        default: fr = 0; fi = 1;  break;
    }
    for (int i = 0; i < D * D; i++) {
        double r = qr[i], im = qi[i];
        qr[i] = r * fr - im * fi;
        qi[i] = r * fi + im * fr;
    }
}

__global__ void w3j_setup_kernel() {
    const int L1[11] = {0, 0, 0, 1, 1, 1, 1, 2, 2, 2, 2};
    const int L2[11] = {0, 1, 2, 0, 1, 1, 2, 0, 1, 2, 2};
    const int L3[11] = {0, 1, 2, 1, 0, 2, 1, 2, 1, 0, 2};
    int t = blockIdx.x;
    int j1 = L1[t], j2 = L2[t], j3 = L3[t];
    int d1 = 2 * j1 + 1, d2 = 2 * j2 + 1, d3 = 2 * j3 + 1;
    __shared__ double Cs[125];
    __shared__ double Q1r[25], Q1i[25], Q2r[25], Q2i[25], Q3r[25], Q3i[25];
    __shared__ double outv[125];
    __shared__ double scale_s;
    int tid = threadIdx.x;
    if (tid < 125) Cs[tid] = 0.0;
    if (tid == 0) {
        build_q(j1, Q1r, Q1i);
        build_q(j2, Q2r, Q2i);
        build_q(j3, Q3r, Q3i);
    }
    __syncthreads();
    if (tid < d1 * d2) {
        int m1 = tid / d2 - j1;
        int m2 = tid % d2 - j2;
        int m3 = m1 + m2;
        if (m3 >= -j3 && m3 <= j3) {
            int vmin = -j1 + j2 + m3;
            if (-j1 + m1 > vmin) vmin = -j1 + m1;
            if (vmin < 0) vmin = 0;
            int vmax = j2 + j3 + m1;
            if (j3 - j1 + j2 < vmax) vmax = j3 - j1 + j2;
            if (j3 + m3 < vmax) vmax = j3 + m3;
            double c = sqrt((double)(2 * j3 + 1) * dfact(j3 + j1 - j2) * dfact(j3 - j1 + j2) *
                            dfact(j1 + j2 - j3) * dfact(j3 + m3) * dfact(j3 - m3) /
                            (dfact(j1 + j2 + j3 + 1) * dfact(j1 - m1) * dfact(j1 + m1) *
                             dfact(j2 - m2) * dfact(j2 + m2)));
            double s = 0.0;
            for (int v = vmin; v <= vmax; v++) {
                double term = dfact(j2 + j3 + m1 - v) * dfact(j1 - m1 + v) /
                              (dfact(v) * dfact(j3 - j1 + j2 - v) * dfact(j3 + m3 - v) *
                               dfact(v + j1 - j2 - m3));
                if ((v + j2 + m2) & 1) term = -term;
                s += term;
            }
            Cs[((m1 + j1) * d2 + (m2 + j2)) * d3 + (m3 + j3)] = c * s;
        }
    }
    __syncthreads();
    int nel = d1 * d2 * d3;
    if (tid < nel) {
        int jj = tid / (d2 * d3);
        int ll = (tid / d3) % d2;
        int mm = tid % d3;
        double ar = 0.0;
        for (int i = 0; i < d1; i++)
            for (int k = 0; k < d2; k++)
                for (int n = 0; n < d3; n++) {
                    double cv = Cs[(i * d2 + k) * d3 + n];
                    if (cv == 0.0) continue;
                    double p1r = Q1r[i * d1 + jj], p1i = Q1i[i * d1 + jj];
                    double p2r = Q2r[k * d2 + ll], p2i = Q2i[k * d2 + ll];
                    double p3r = Q3r[n * d3 + mm], p3i = -Q3i[n * d3 + mm];
                    double t1r = p1r * p2r - p1i * p2i;
                    double t1i = p1r * p2i + p1i * p2r;
                    double t2r = t1r * p3r - t1i * p3i;
                    ar += t2r * cv;
                }
        outv[tid] = ar;
    }
    __syncthreads();
    if (tid == 0) {
        const double PWv[3] = {0.10206207261596575, 0.15309310892394862, 0.19764235376052370};
        double s = 0.0;
        for (int i = 0; i < nel; i++) s += outv[i] * outv[i];
        scale_s = PWv[j3] / sqrt(s);
    }
    __syncthreads();
    if (tid < nel) g_w3j[t * 125 + tid] = (float)(outv[tid] * scale_s);
}

// ======================= W2 relayout into fp16 B-fragment order =======================
// src: W2[c][col], col = ins*1024 + u*32 + w; scaled by 1/8, fp16-rounded.
// m16n8k16 B fragment: b0 halves = B[k=2tig, 2tig+1][n=g], b1 = B[k=2tig+8, 2tig+9][n=g],
// per 16-k chunk q (4 chunks for K=64). Two uint4 per (u,wtile,lane): q2 = q>>1 selects which,
// uint32 slot within uint4 = (q&1)*2 + hsel.
__global__ void w2h_kernel(const float* __restrict__ W2) {
    int idx = blockIdx.x * 256 + threadIdx.x;
    if (idx >= 64 * 11264) return;
    int c = idx / 11264;
    int col = idx - c * 11264;
    int ins = col >> 10;
    int rem = col & 1023;
    int u = rem >> 5;
    int w = rem & 31;
    int wtile = w >> 3, n = w & 7;
    int q = c >> 4, cl = c & 15;
    int hsel = cl >> 3;
    int c8 = cl & 7;
    int tig = c8 >> 1, pp = c8 & 1;
    int lane = (n << 2) | tig;
    int q2 = q >> 1, qq = q & 1;
    int u4 = (((ins * 32 + u) * 4 + wtile) * 2 + q2) * 32 + lane;
    int hidx = u4 * 8 + (qq * 2 + hsel) * 2 + pp;
    ((__half*)g_W2H)[hidx] = __float2half(W2[idx] * 0.125f);
}

// ======================= weight-NN hidden layer (fp16 output) =======================
__global__ void h_kernel(const float* __restrict__ radial, const float* __restrict__ W1,
                         float cst, int E) {
    __shared__ float rs[4][64];
    int le = threadIdx.x >> 6, c = threadIdx.x & 63;
    int e = blockIdx.x * 4 + le;
    rs[le][c] = (e < E) ? radial[e * 64 + c] : 0.f;
    __syncthreads();
    float a = 0.f;
#pragma unroll
    for (int r = 0; r < 64; r++) a += rs[le][r] * W1[r * 64 + c];
    a *= 0.125f;  // 1/sqrt(64)
    float hv = cst * a / (1.f + expf(-a));
    if (e < E) g_Hh[e * 64 + c] = __float2half(hv);
}

// ======================= self-connection (writes d_out, clears poison) =======================
__global__ void sc_kernel(const float* __restrict__ nf, const float* __restrict__ w0,
                          const float* __restrict__ w1, const float* __restrict__ w2,
                          float* __restrict__ out) {
    __shared__ float xrow[288];
    int n = blockIdx.x;
    int t = threadIdx.x;
    xrow[t] = nf[n * 288 + t];
    __syncthreads();
    int O, d, wch, k;
    const float* W;
    if (t < 32)       { O = 0;   d = 1; wch = t;          k = 0;            W = w0; }
    else if (t < 128) { int r = t - 32;  O = 32;  d = 3; wch = r / 3; k = r - wch * 3; W = w1; }
    else              { int r = t - 128; O = 128; d = 5; wch = r / 5; k = r - wch * 5; W = w2; }
    float a = 0.f;
#pragma unroll
    for (int u = 0; u < 32; u++) a += xrow[O + u * d + k] * W[u * 32 + wch];
    out[n * 288 + t] = a * 0.17677669529663687f;  // 1/sqrt(32)
}

// ======================= fused message kernel (fp16 MMA, 64-edge tiles) =======================
// Warp wid: wtile = wid&3, half = wid>>2; owns row-tiles {2*half, 2*half+1} and w-cols [wtile*8,+8).
// Lane: g = lane>>2, tig = lane&3. Row-tile t rows: ert, ert+8. Cols wc0 = wtile*8+2tig, wc1=wc0+1.
template <int D1, int D2, int D3, int SO2, int O1, int KO, int W3OFF, int PB>
__device__ __forceinline__ void process_ins(float* __restrict__ xs,
                                            float* __restrict__ zs, float* __restrict__ ss,
                                            const float* __restrict__ shT,
                                            const uint32_t (&af)[2][4][4], float (&acc)[8][9],
                                            int tid, int lane, int wtile,
                                            const int (&ert)[2]) {
    // B prefetch for u=0 (no smem dependency — issue before the barrier)
    const uint4* __restrict__ Bp = g_W2H + PB + wtile * 64 + lane;
    uint4 Bc0 = __ldg(Bp), Bc1 = __ldg(Bp + 32);
    uint4 Bn0, Bn1;

    __syncthreads();  // protect ss/zs reuse
    // s[e,i,k] = sum_j w3j[i,j,k] * sh[e,j]
    for (int idx = tid; idx < TEDGE * D1 * D3; idx += NTHR) {
        int e = idx & (TEDGE - 1);
        int r = idx >> 6;
        int i = r / D3;
        int k = r - i * D3;
        float a = 0.f;
#pragma unroll
        for (int j = 0; j < D2; j++)
            a += g_w3j[W3OFF + (i * D2 + j) * D3 + k] * shT[(SO2 + j) * EPAD + e];
        ss[(i * D3 + k) * EPAD + e] = a;
    }
    __syncthreads();
    // z[e,u,k] = sum_i x[e,u,i] * s[e,i,k]
    for (int idx = tid; idx < TEDGE * 32; idx += NTHR) {
        int e = idx & (TEDGE - 1);
        int u = idx >> 6;
        float xv[D1];
#pragma unroll
        for (int i = 0; i < D1; i++) xv[i] = xs[(O1 + u * D1 + i) * EPAD + e];
#pragma unroll
        for (int k = 0; k < D3; k++) {
            float z = 0.f;
#pragma unroll
            for (int i = 0; i < D1; i++) z += xv[i] * ss[(i * D3 + k) * EPAD + e];
            zs[(u * D3 + k) * EPAD + e] = z;
        }
    }
    __syncthreads();
    // MMA: wv fragment per u (shared across both row-tiles), consumed immediately against z.
#pragma unroll 1
    for (int u = 0; u < 32; u++) {
        if (u < 31) {
            const uint4* __restrict__ Bu = Bp + (u + 1) * 256;
            Bn0 = __ldg(Bu);
            Bn1 = __ldg(Bu + 32);
        }
#pragma unroll
        for (int t = 0; t < 2; t++) {
            float c0[4] = {0.f, 0.f, 0.f, 0.f};
            float c1[4] = {0.f, 0.f, 0.f, 0.f};
            mma_f16(c0, af[t][0], Bc0.x, Bc0.y);
            mma_f16(c1, af[t][1], Bc0.z, Bc0.w);
            mma_f16(c0, af[t][2], Bc1.x, Bc1.y);
            mma_f16(c1, af[t][3], Bc1.z, Bc1.w);
            float wv0 = c0[0] + c1[0];
            float wv1 = c0[1] + c1[1];
            float wv2 = c0[2] + c1[2];
            float wv3 = c0[3] + c1[3];
            int er0 = ert[t], er1 = ert[t] + 8;
#pragma unroll
            for (int k = 0; k < D3; k++) {
                float z0 = zs[(u * D3 + k) * EPAD + er0];
                float z1 = zs[(u * D3 + k) * EPAD + er1];
                acc[t * 4 + 0][KO + k] += wv0 * z0;
                acc[t * 4 + 1][KO + k] += wv1 * z0;
                acc[t * 4 + 2][KO + k] += wv2 * z1;
                acc[t * 4 + 3][KO + k] += wv3 * z1;
            }
        }
        Bc0 = Bn0;
        Bc1 = Bn1;
    }
}

#define PINS(IDX, A, B, Cc)                                                                   \
    process_ins<DIMS_[A], DIMS_[B], DIMS_[Cc], SO_[B], OFF_[A], KO_[Cc], IDX * 125,           \
                IDX * 8192>(xs, zs, ss, shT, af, acc, tid, lane, wtile, ert)

__global__ void __launch_bounds__(NTHR, 1)
msg_kernel(const float* __restrict__ nf, const int* __restrict__ ei,
           const float* __restrict__ shg, float* __restrict__ out, int E) {
    extern __shared__ float smem[];
    float* xs   = smem;                         // 288*65 floats
    __half* hsm = (__half*)(xs + 288 * EPAD);   // 64*64 halves (= TEDGE*32 floats)
    float* zs   = xs + 288 * EPAD + TEDGE * 32; // 32*5*65 floats
    float* ss   = zs + 32 * 5 * EPAD;           // 25*65
    float* shT  = ss + 25 * EPAD;               // 9*65
    int* srcdst = (int*)(shT + 9 * EPAD);       // 128 ints
    int tid = threadIdx.x;
    int e0 = blockIdx.x * TEDGE;

    if (tid < 128) {
        int e = e0 + (tid & 63);
        int which = tid >> 6;
        srcdst[tid] = (e < E) ? ei[which * E + e] : 0;
    }
    __syncthreads();
    for (int idx = tid; idx < TEDGE * 288; idx += NTHR) {
        int e = idx / 288;
        int c = idx - e * 288;
        xs[c * EPAD + e] = (e0 + e < E) ? nf[srcdst[e] * 288 + c] : 0.f;
    }
    for (int idx = tid; idx < TEDGE * 64; idx += NTHR) {
        int e = idx >> 6;
        int c = idx & 63;
        hsm[e * 64 + c] = (e0 + e < E) ? g_Hh[(e0 + e) * 64 + c] : __float2half(0.f);
    }
    for (int idx = tid; idx < TEDGE * 9; idx += NTHR) {
        int e = idx & 63;
        int j = idx >> 6;
        shT[j * EPAD + e] = (e0 + e < E) ? shg[(e0 + e) * 9 + j] : 0.f;
    }
    __syncthreads();  // hsm ready for A-fragment build

    int lane = tid & 31;
    int wid = tid >> 5;
    int half = wid >> 2, wtile = wid & 3;
    int g = lane >> 2, tig = lane & 3;
    int ert[2] = {(2 * half) * 16 + g, (2 * half + 1) * 16 + g};
    int wc0 = wtile * 8 + 2 * tig, wc1 = wc0 + 1;

    // A fragments (h, fp16 half2-packed) for both row-tiles, resident all kernel.
    // Chunk q covers k=[16q,16q+16): a0/a1 = rows er/er+8 k=2tig..; a2/a3 = +8 in k.
    const uint32_t* hs2 = (const uint32_t*)hsm;
    uint32_t af[2][4][4];
#pragma unroll
    for (int t = 0; t < 2; t++)
#pragma unroll
        for (int q = 0; q < 4; q++) {
            af[t][q][0] = hs2[ert[t] * 32 + q * 8 + tig];
            af[t][q][1] = hs2[(ert[t] + 8) * 32 + q * 8 + tig];
            af[t][q][2] = hs2[ert[t] * 32 + q * 8 + 4 + tig];
            af[t][q][3] = hs2[(ert[t] + 8) * 32 + q * 8 + 4 + tig];
        }

    float acc[8][9];
#pragma unroll
    for (int p = 0; p < 8; p++)
#pragma unroll
        for (int k = 0; k < 9; k++) acc[p][k] = 0.f;

    PINS(0, 0, 0, 0); PINS(1, 0, 1, 1); PINS(2, 0, 2, 2); PINS(3, 1, 0, 1);
    PINS(4, 1, 1, 0); PINS(5, 1, 1, 2); PINS(6, 1, 2, 1); PINS(7, 2, 0, 2);
    PINS(8, 2, 1, 1); PINS(9, 2, 2, 0); PINS(10, 2, 2, 2);

    const float inv = 0.31622776601683794f;  // 1/sqrt(NUM_NEIGHBORS)
#pragma unroll
    for (int t = 0; t < 2; t++) {
#pragma unroll
        for (int p = 0; p < 4; p++) {
            int e = ert[t] + ((p & 2) ? 8 : 0);
            int wcol = (p & 1) ? wc1 : wc0;
            if (e0 + e >= E) continue;
            int node = srcdst[64 + e];
            float* op = out + node * 288;
            float* ac = acc[t * 4 + p];
            atomicAdd(op + wcol, inv * ac[0]);
#pragma unroll
            for (int k = 0; k < 3; k++) atomicAdd(op + 32 + wcol * 3 + k, inv * ac[1 + k]);
#pragma unroll
            for (int k = 0; k < 5; k++) atomicAdd(op + 128 + wcol * 5 + k, inv * ac[4 + k]);
        }
    }
}

// ======================= host: numpy RandomState(0) SILU_CST reproduction =======================
namespace {
struct NpRng {
    uint32_t mt[624];
    int mti;
    bool has_g;
    double g;
};
inline void rng_seed(NpRng& s, uint32_t sd) {
    s.mt[0] = sd;
    for (int i = 1; i < 624; i++)
        s.mt[i] = 1812433253u * (s.mt[i - 1] ^ (s.mt[i - 1] >> 30)) + (uint32_t)i;
    s.mti = 624;
    s.has_g = false;
    s.g = 0.0;
}
inline uint32_t rng_u32(NpRng& s) {
    if (s.mti >= 624) {
        for (int i = 0; i < 624; i++) {
            uint32_t y = (s.mt[i] & 0x80000000u) | (s.mt[(i + 1) % 624] & 0x7fffffffu);
            s.mt[i] = s.mt[(i + 397) % 624] ^ (y >> 1) ^ ((y & 1u) ? 0x9908b0dfu : 0u);
        }
        s.mti = 0;
    }
    uint32_t y = s.mt[s.mti++];
    y ^= y >> 11;
    y ^= (y << 7) & 0x9d2c5680u;
    y ^= (y << 15) & 0xefc60000u;
    y ^= y >> 18;
    return y;
}
inline double rng_double(NpRng& s) {
    uint32_t a = rng_u32(s) >> 5;
    uint32_t b = rng_u32(s) >> 6;
    return ((double)a * 67108864.0 + (double)b) / 9007199254740992.0;
}
inline double rng_gauss(NpRng& s) {
    if (s.has_g) {
        s.has_g = false;
        return s.g;
    }
    double x1, x2, r2;
    do {
        x1 = 2.0 * rng_double(s) - 1.0;
        x2 = 2.0 * rng_double(s) - 1.0;
        r2 = x1 * x1 + x2 * x2;
    } while (r2 >= 1.0 || r2 == 0.0);
    double f = sqrt(-2.0 * log(r2) / r2);
    s.g = f * x1;
    s.has_g = true;
    return f * x2;
}
inline double compute_silu_cst() {
    NpRng s;
    rng_seed(s, 0u);
    double sum = 0.0;
    for (int i = 0; i < 1000000; i++) {
        double z = rng_gauss(s);
        double sl = z / (1.0 + exp(-z));
        sum += sl * sl;
    }
    return 1.0 / sqrt(sum / 1000000.0);
}
}  // namespace

// ======================= launch =======================
extern "C" void kernel_launch(void* const* d_in, const int* in_sizes, int n_in,
                              void* d_out, int out_size) {
    const float* nf     = (const float*)d_in[0];
    const int*   ei     = (const int*)d_in[1];
    const float* sh     = (const float*)d_in[2];
    const float* radial = (const float*)d_in[3];
    const float* W1     = (const float*)d_in[4];
    const float* W2     = (const float*)d_in[5];
    const float* Wsc0   = (const float*)d_in[6];
    const float* Wsc1   = (const float*)d_in[7];
    const float* Wsc2   = (const float*)d_in[8];
    float* out = (float*)d_out;
    int N = in_sizes[0] / 288;
    int E = in_sizes[1] / 2;

    float cst = (float)compute_silu_cst();

    const size_t SMEM = (288 * EPAD + TEDGE * 32 + 32 * 5 * EPAD + 25 * EPAD + 9 * EPAD) * 4
                        + 128 * 4;  // ~134 KB
    cudaFuncSetAttribute(msg_kernel, cudaFuncAttributeMaxDynamicSharedMemorySize, (int)SMEM);

    w3j_setup_kernel<<<11, 128>>>();
    w2h_kernel<<<(64 * 11264 + 255) / 256, 256>>>(W2);
    h_kernel<<<(E + 3) / 4, 256>>>(radial, W1, cst, E);
    sc_kernel<<<N, 288>>>(nf, Wsc0, Wsc1, Wsc2, out);
    msg_kernel<<<(E + TEDGE - 1) / TEDGE, NTHR, SMEM>>>(nf, ei, sh, out, E);
}

// round 8
// speedup vs baseline: 11.6785x; 1.0374x over previous
#include <cuda_runtime.h>
#include <cuda_fp16.h>
#include <math.h>
#include <stdint.h>

#define NTHR 512
#define TEDGE 64
#define EPAD 65

// ---------------- device scratch (static, no allocation) ----------------
__device__ float g_w3j[11 * 125];        // per-instruction wigner3j, pre-scaled by PW[l3]
__device__ uint4 g_W2H[11 * 32 * 4 * 2 * 32];  // W2 in fp16 B-fragment layout (1.44 MB)
__device__ __half g_Hh[20000 * 64];      // weight-NN hidden activations (fp16)

// irrep constants
constexpr int DIMS_[3] = {1, 3, 5};
constexpr int OFF_[3]  = {0, 32, 128};  // offsets into 288-dim feature
constexpr int SO_[3]   = {0, 1, 4};     // offsets into 9-dim sh
constexpr int KO_[3]   = {0, 1, 4};     // offsets into 9-slot accumulator

// fp16 m16n8k16 MMA, D += A*B (fp32 accumulate)
__device__ __forceinline__ void mma_f16(float* d, const uint32_t* a, uint32_t b0, uint32_t b1) {
    asm volatile(
        "mma.sync.aligned.m16n8k16.row.col.f32.f16.f16.f32 "
        "{%0,%1,%2,%3}, {%4,%5,%6,%7}, {%8,%9}, {%0,%1,%2,%3};\n"
        : "+f"(d[0]), "+f"(d[1]), "+f"(d[2]), "+f"(d[3])
        : "r"(a[0]), "r"(a[1]), "r"(a[2]), "r"(a[3]), "r"(b0), "r"(b1));
}

// ======================= wigner-3j setup (reference algorithm) =======================
__device__ __forceinline__ double dfact(int n) {
    double r = 1.0;
    for (int i = 2; i <= n; i++) r *= (double)i;
    return r;
}

__device__ void build_q(int l, double* qr, double* qi) {
    int D = 2 * l + 1;
    for (int i = 0; i < D * D; i++) { qr[i] = 0.0; qi[i] = 0.0; }
    const double s2 = 0.70710678118654752440;
    for (int m = -l; m < 0; m++) {
        qr[(l + m) * D + (l - m)] = s2;
        qi[(l + m) * D + (l + m)] = -s2;
    }
    qr[l * D + l] = 1.0;
    for (int m = 1; m <= l; m++) {
        double sg = (m & 1) ? -1.0 : 1.0;
        qr[(l + m) * D + (l + m)] = sg * s2;
        qi[(l + m) * D + (l - m)] = sg * s2;
    }
    double fr, fi;
    switch (l & 3) {
        case 0: fr = 1;  fi = 0;  break;
        case 1: fr = 0;  fi = -1; break;
        case 2: fr = -1; fi = 0;  break;
        default: fr = 0; fi = 1;  break;
    }
    for (int i = 0; i < D * D; i++) {
        double r = qr[i], im = qi[i];
        qr[i] = r * fr - im * fi;
        qi[i] = r * fi + im * fr;
    }
}

__global__ void w3j_setup_kernel() {
    const int L1[11] = {0, 0, 0, 1, 1, 1, 1, 2, 2, 2, 2};
    const int L2[11] = {0, 1, 2, 0, 1, 1, 2, 0, 1, 2, 2};
    const int L3[11] = {0, 1, 2, 1, 0, 2, 1, 2, 1, 0, 2};
    int t = blockIdx.x;
    int j1 = L1[t], j2 = L2[t], j3 = L3[t];
    int d1 = 2 * j1 + 1, d2 = 2 * j2 + 1, d3 = 2 * j3 + 1;
    __shared__ double Cs[125];
    __shared__ double Q1r[25], Q1i[25], Q2r[25], Q2i[25], Q3r[25], Q3i[25];
    __shared__ double outv[125];
    __shared__ double scale_s;
    int tid = threadIdx.x;
    if (tid < 125) Cs[tid] = 0.0;
    if (tid == 0) {
        build_q(j1, Q1r, Q1i);
        build_q(j2, Q2r, Q2i);
        build_q(j3, Q3r, Q3i);
    }
    __syncthreads();
    if (tid < d1 * d2) {
        int m1 = tid / d2 - j1;
        int m2 = tid % d2 - j2;
        int m3 = m1 + m2;
        if (m3 >= -j3 && m3 <= j3) {
            int vmin = -j1 + j2 + m3;
            if (-j1 + m1 > vmin) vmin = -j1 + m1;
            if (vmin < 0) vmin = 0;
            int vmax = j2 + j3 + m1;
            if (j3 - j1 + j2 < vmax) vmax = j3 - j1 + j2;
            if (j3 + m3 < vmax) vmax = j3 + m3;
            double c = sqrt((double)(2 * j3 + 1) * dfact(j3 + j1 - j2) * dfact(j3 - j1 + j2) *
                            dfact(j1 + j2 - j3) * dfact(j3 + m3) * dfact(j3 - m3) /
                            (dfact(j1 + j2 + j3 + 1) * dfact(j1 - m1) * dfact(j1 + m1) *
                             dfact(j2 - m2) * dfact(j2 + m2)));
            double s = 0.0;
            for (int v = vmin; v <= vmax; v++) {
                double term = dfact(j2 + j3 + m1 - v) * dfact(j1 - m1 + v) /
                              (dfact(v) * dfact(j3 - j1 + j2 - v) * dfact(j3 + m3 - v) *
                               dfact(v + j1 - j2 - m3));
                if ((v + j2 + m2) & 1) term = -term;
                s += term;
            }
            Cs[((m1 + j1) * d2 + (m2 + j2)) * d3 + (m3 + j3)] = c * s;
        }
    }
    __syncthreads();
    int nel = d1 * d2 * d3;
    if (tid < nel) {
        int jj = tid / (d2 * d3);
        int ll = (tid / d3) % d2;
        int mm = tid % d3;
        double ar = 0.0;
        for (int i = 0; i < d1; i++)
            for (int k = 0; k < d2; k++)
                for (int n = 0; n < d3; n++) {
                    double cv = Cs[(i * d2 + k) * d3 + n];
                    if (cv == 0.0) continue;
                    double p1r = Q1r[i * d1 + jj], p1i = Q1i[i * d1 + jj];
                    double p2r = Q2r[k * d2 + ll], p2i = Q2i[k * d2 + ll];
                    double p3r = Q3r[n * d3 + mm], p3i = -Q3i[n * d3 + mm];
                    double t1r = p1r * p2r - p1i * p2i;
                    double t1i = p1r * p2i + p1i * p2r;
                    double t2r = t1r * p3r - t1i * p3i;
                    ar += t2r * cv;
                }
        outv[tid] = ar;
    }
    __syncthreads();
    if (tid == 0) {
        const double PWv[3] = {0.10206207261596575, 0.15309310892394862, 0.19764235376052370};
        double s = 0.0;
        for (int i = 0; i < nel; i++) s += outv[i] * outv[i];
        scale_s = PWv[j3] / sqrt(s);
    }
    __syncthreads();
    if (tid < nel) g_w3j[t * 125 + tid] = (float)(outv[tid] * scale_s);
}

// ======================= W2 relayout into fp16 B-fragment order =======================
// src: W2[c][col], col = ins*1024 + u*32 + w; scaled by 1/8, fp16-rounded.
__global__ void w2h_kernel(const float* __restrict__ W2) {
    int idx = blockIdx.x * 256 + threadIdx.x;
    if (idx >= 64 * 11264) return;
    int c = idx / 11264;
    int col = idx - c * 11264;
    int ins = col >> 10;
    int rem = col & 1023;
    int u = rem >> 5;
    int w = rem & 31;
    int wtile = w >> 3, n = w & 7;
    int q = c >> 4, cl = c & 15;
    int hsel = cl >> 3;
    int c8 = cl & 7;
    int tig = c8 >> 1, pp = c8 & 1;
    int lane = (n << 2) | tig;
    int q2 = q >> 1, qq = q & 1;
    int u4 = (((ins * 32 + u) * 4 + wtile) * 2 + q2) * 32 + lane;
    int hidx = u4 * 8 + (qq * 2 + hsel) * 2 + pp;
    ((__half*)g_W2H)[hidx] = __float2half(W2[idx] * 0.125f);
}

// ======================= weight-NN hidden layer (fp16 output) =======================
__global__ void h_kernel(const float* __restrict__ radial, const float* __restrict__ W1,
                         float cst, int E) {
    __shared__ float rs[4][64];
    int le = threadIdx.x >> 6, c = threadIdx.x & 63;
    int e = blockIdx.x * 4 + le;
    rs[le][c] = (e < E) ? radial[e * 64 + c] : 0.f;
    __syncthreads();
    float a = 0.f;
#pragma unroll
    for (int r = 0; r < 64; r++) a += rs[le][r] * W1[r * 64 + c];
    a *= 0.125f;  // 1/sqrt(64)
    float hv = cst * a / (1.f + expf(-a));
    if (e < E) g_Hh[e * 64 + c] = __float2half(hv);
}

// ======================= self-connection (writes d_out, clears poison) =======================
__global__ void sc_kernel(const float* __restrict__ nf, const float* __restrict__ w0,
                          const float* __restrict__ w1, const float* __restrict__ w2,
                          float* __restrict__ out) {
    __shared__ float xrow[288];
    int n = blockIdx.x;
    int t = threadIdx.x;
    xrow[t] = nf[n * 288 + t];
    __syncthreads();
    int O, d, wch, k;
    const float* W;
    if (t < 32)       { O = 0;   d = 1; wch = t;          k = 0;            W = w0; }
    else if (t < 128) { int r = t - 32;  O = 32;  d = 3; wch = r / 3; k = r - wch * 3; W = w1; }
    else              { int r = t - 128; O = 128; d = 5; wch = r / 5; k = r - wch * 5; W = w2; }
    float a = 0.f;
#pragma unroll
    for (int u = 0; u < 32; u++) a += xrow[O + u * d + k] * W[u * 32 + wch];
    out[n * 288 + t] = a * 0.17677669529663687f;  // 1/sqrt(32)
}

// ======================= fused message kernel (fp16 MMA, 64 edges, 16 warps) =======================
// Block = 512 threads = 16 warps. Warp wid: wtile = wid&3, rtile = wid>>2 (0..3).
// Warp owns row-tile rtile (16 edges) x w-cols [wtile*8, wtile*8+8).
// Lane: g = lane>>2, tig = lane&3. Rows er0 = rtile*16+g, er1 = er0+8.
// Cols wc0 = wtile*8 + 2*tig, wc1 = wc0+1.
// acc[p][9]: p0:(er0,wc0) p1:(er0,wc1) p2:(er1,wc0) p3:(er1,wc1).
template <int D1, int D2, int D3, int SO2, int O1, int KO, int W3OFF, int PB>
__device__ __forceinline__ void process_ins(float* __restrict__ xs,
                                            float* __restrict__ zs, float* __restrict__ ss,
                                            const float* __restrict__ shT,
                                            const uint32_t (&af)[4][4], float (&acc)[4][9],
                                            int tid, int lane, int wtile,
                                            int er0, int er1) {
    // B prefetch for u=0 (no smem dependency — issue before the barrier)
    const uint4* __restrict__ Bp = g_W2H + PB + wtile * 64 + lane;
    uint4 Bc0 = __ldg(Bp), Bc1 = __ldg(Bp + 32);
    uint4 Bn0, Bn1;

    __syncthreads();  // protect ss/zs reuse
    // s[e,i,k] = sum_j w3j[i,j,k] * sh[e,j]
    for (int idx = tid; idx < TEDGE * D1 * D3; idx += NTHR) {
        int e = idx & (TEDGE - 1);
        int r = idx >> 6;
        int i = r / D3;
        int k = r - i * D3;
        float a = 0.f;
#pragma unroll
        for (int j = 0; j < D2; j++)
            a += g_w3j[W3OFF + (i * D2 + j) * D3 + k] * shT[(SO2 + j) * EPAD + e];
        ss[(i * D3 + k) * EPAD + e] = a;
    }
    __syncthreads();
    // z[e,u,k] = sum_i x[e,u,i] * s[e,i,k]
    for (int idx = tid; idx < TEDGE * 32; idx += NTHR) {
        int e = idx & (TEDGE - 1);
        int u = idx >> 6;
        float xv[D1];
#pragma unroll
        for (int i = 0; i < D1; i++) xv[i] = xs[(O1 + u * D1 + i) * EPAD + e];
#pragma unroll
        for (int k = 0; k < D3; k++) {
            float z = 0.f;
#pragma unroll
            for (int i = 0; i < D1; i++) z += xv[i] * ss[(i * D3 + k) * EPAD + e];
            zs[(u * D3 + k) * EPAD + e] = z;
        }
    }
    __syncthreads();
    // MMA: wv fragment per u, consumed immediately against z.
#pragma unroll 1
    for (int u = 0; u < 32; u++) {
        if (u < 31) {
            const uint4* __restrict__ Bu = Bp + (u + 1) * 256;
            Bn0 = __ldg(Bu);
            Bn1 = __ldg(Bu + 32);
        }
        float c0[4] = {0.f, 0.f, 0.f, 0.f};
        float c1[4] = {0.f, 0.f, 0.f, 0.f};
        mma_f16(c0, af[0], Bc0.x, Bc0.y);
        mma_f16(c1, af[1], Bc0.z, Bc0.w);
        mma_f16(c0, af[2], Bc1.x, Bc1.y);
        mma_f16(c1, af[3], Bc1.z, Bc1.w);
        float wv0 = c0[0] + c1[0];
        float wv1 = c0[1] + c1[1];
        float wv2 = c0[2] + c1[2];
        float wv3 = c0[3] + c1[3];
#pragma unroll
        for (int k = 0; k < D3; k++) {
            float z0 = zs[(u * D3 + k) * EPAD + er0];
            float z1 = zs[(u * D3 + k) * EPAD + er1];
            acc[0][KO + k] += wv0 * z0;
            acc[1][KO + k] += wv1 * z0;
            acc[2][KO + k] += wv2 * z1;
            acc[3][KO + k] += wv3 * z1;
        }
        Bc0 = Bn0;
        Bc1 = Bn1;
    }
}

#define PINS(IDX, A, B, Cc)                                                                   \
    process_ins<DIMS_[A], DIMS_[B], DIMS_[Cc], SO_[B], OFF_[A], KO_[Cc], IDX * 125,           \
                IDX * 8192>(xs, zs, ss, shT, af, acc, tid, lane, wtile, er0, er1)

__global__ void __launch_bounds__(NTHR, 1)
msg_kernel(const float* __restrict__ nf, const int* __restrict__ ei,
           const float* __restrict__ shg, float* __restrict__ out, int E) {
    extern __shared__ float smem[];
    float* xs   = smem;                         // 288*65 floats
    __half* hsm = (__half*)(xs + 288 * EPAD);   // 64*64 halves (= TEDGE*32 floats)
    float* zs   = xs + 288 * EPAD + TEDGE * 32; // 32*5*65 floats
    float* ss   = zs + 32 * 5 * EPAD;           // 25*65
    float* shT  = ss + 25 * EPAD;               // 9*65
    int* srcdst = (int*)(shT + 9 * EPAD);       // 128 ints
    int tid = threadIdx.x;
    int e0 = blockIdx.x * TEDGE;

    if (tid < 128) {
        int e = e0 + (tid & 63);
        int which = tid >> 6;
        srcdst[tid] = (e < E) ? ei[which * E + e] : 0;
    }
    __syncthreads();
    for (int idx = tid; idx < TEDGE * 288; idx += NTHR) {
        int e = idx / 288;
        int c = idx - e * 288;
        xs[c * EPAD + e] = (e0 + e < E) ? nf[srcdst[e] * 288 + c] : 0.f;
    }
    for (int idx = tid; idx < TEDGE * 64; idx += NTHR) {
        int e = idx >> 6;
        int c = idx & 63;
        hsm[e * 64 + c] = (e0 + e < E) ? g_Hh[(e0 + e) * 64 + c] : __float2half(0.f);
    }
    for (int idx = tid; idx < TEDGE * 9; idx += NTHR) {
        int e = idx & 63;
        int j = idx >> 6;
        shT[j * EPAD + e] = (e0 + e < E) ? shg[(e0 + e) * 9 + j] : 0.f;
    }
    __syncthreads();  // hsm ready for A-fragment build

    int lane = tid & 31;
    int wid = tid >> 5;
    int rtile = wid >> 2, wtile = wid & 3;
    int g = lane >> 2, tig = lane & 3;
    int er0 = rtile * 16 + g, er1 = er0 + 8;
    int wc0 = wtile * 8 + 2 * tig, wc1 = wc0 + 1;

    // A fragments (h, fp16 half2-packed), resident all kernel.
    const uint32_t* hs2 = (const uint32_t*)hsm;
    uint32_t af[4][4];
#pragma unroll
    for (int q = 0; q < 4; q++) {
        af[q][0] = hs2[er0 * 32 + q * 8 + tig];
        af[q][1] = hs2[er1 * 32 + q * 8 + tig];
        af[q][2] = hs2[er0 * 32 + q * 8 + 4 + tig];
        af[q][3] = hs2[er1 * 32 + q * 8 + 4 + tig];
    }

    float acc[4][9];
#pragma unroll
    for (int p = 0; p < 4; p++)
#pragma unroll
        for (int k = 0; k < 9; k++) acc[p][k] = 0.f;

    PINS(0, 0, 0, 0); PINS(1, 0, 1, 1); PINS(2, 0, 2, 2); PINS(3, 1, 0, 1);
    PINS(4, 1, 1, 0); PINS(5, 1, 1, 2); PINS(6, 1, 2, 1); PINS(7, 2, 0, 2);
    PINS(8, 2, 1, 1); PINS(9, 2, 2, 0); PINS(10, 2, 2, 2);

    const float inv = 0.31622776601683794f;  // 1/sqrt(NUM_NEIGHBORS)
#pragma unroll
    for (int p = 0; p < 4; p++) {
        int e = (p & 2) ? er1 : er0;
        int wcol = (p & 1) ? wc1 : wc0;
        if (e0 + e >= E) continue;
        int node = srcdst[64 + e];
        float* op = out + node * 288;
        float* ac = acc[p];
        atomicAdd(op + wcol, inv * ac[0]);
#pragma unroll
        for (int k = 0; k < 3; k++) atomicAdd(op + 32 + wcol * 3 + k, inv * ac[1 + k]);
#pragma unroll
        for (int k = 0; k < 5; k++) atomicAdd(op + 128 + wcol * 5 + k, inv * ac[4 + k]);
    }
}

// ======================= host: numpy RandomState(0) SILU_CST reproduction =======================
namespace {
struct NpRng {
    uint32_t mt[624];
    int mti;
    bool has_g;
    double g;
};
inline void rng_seed(NpRng& s, uint32_t sd) {
    s.mt[0] = sd;
    for (int i = 1; i < 624; i++)
        s.mt[i] = 1812433253u * (s.mt[i - 1] ^ (s.mt[i - 1] >> 30)) + (uint32_t)i;
    s.mti = 624;
    s.has_g = false;
    s.g = 0.0;
}
inline uint32_t rng_u32(NpRng& s) {
    if (s.mti >= 624) {
        for (int i = 0; i < 624; i++) {
            uint32_t y = (s.mt[i] & 0x80000000u) | (s.mt[(i + 1) % 624] & 0x7fffffffu);
            s.mt[i] = s.mt[(i + 397) % 624] ^ (y >> 1) ^ ((y & 1u) ? 0x9908b0dfu : 0u);
        }
        s.mti = 0;
    }
    uint32_t y = s.mt[s.mti++];
    y ^= y >> 11;
    y ^= (y << 7) & 0x9d2c5680u;
    y ^= (y << 15) & 0xefc60000u;
    y ^= y >> 18;
    return y;
}
inline double rng_double(NpRng& s) {
    uint32_t a = rng_u32(s) >> 5;
    uint32_t b = rng_u32(s) >> 6;
    return ((double)a * 67108864.0 + (double)b) / 9007199254740992.0;
}
inline double rng_gauss(NpRng& s) {
    if (s.has_g) {
        s.has_g = false;
        return s.g;
    }
    double x1, x2, r2;
    do {
        x1 = 2.0 * rng_double(s) - 1.0;
        x2 = 2.0 * rng_double(s) - 1.0;
        r2 = x1 * x1 + x2 * x2;
    } while (r2 >= 1.0 || r2 == 0.0);
    double f = sqrt(-2.0 * log(r2) / r2);
    s.g = f * x1;
    s.has_g = true;
    return f * x2;
}
inline double compute_silu_cst() {
    NpRng s;
    rng_seed(s, 0u);
    double sum = 0.0;
    for (int i = 0; i < 1000000; i++) {
        double z = rng_gauss(s);
        double sl = z / (1.0 + exp(-z));
        sum += sl * sl;
    }
    return 1.0 / sqrt(sum / 1000000.0);
}
}  // namespace

// ======================= launch =======================
extern "C" void kernel_launch(void* const* d_in, const int* in_sizes, int n_in,
                              void* d_out, int out_size) {
    const float* nf     = (const float*)d_in[0];
    const int*   ei     = (const int*)d_in[1];
    const float* sh     = (const float*)d_in[2];
    const float* radial = (const float*)d_in[3];
    const float* W1     = (const float*)d_in[4];
    const float* W2     = (const float*)d_in[5];
    const float* Wsc0   = (const float*)d_in[6];
    const float* Wsc1   = (const float*)d_in[7];
    const float* Wsc2   = (const float*)d_in[8];
    float* out = (float*)d_out;
    int N = in_sizes[0] / 288;
    int E = in_sizes[1] / 2;

    float cst = (float)compute_silu_cst();

    const size_t SMEM = (288 * EPAD + TEDGE * 32 + 32 * 5 * EPAD + 25 * EPAD + 9 * EPAD) * 4
                        + 128 * 4;  // ~134 KB
    cudaFuncSetAttribute(msg_kernel, cudaFuncAttributeMaxDynamicSharedMemorySize, (int)SMEM);

    w3j_setup_kernel<<<11, 128>>>();
    w2h_kernel<<<(64 * 11264 + 255) / 256, 256>>>(W2);
    h_kernel<<<(E + 3) / 4, 256>>>(radial, W1, cst, E);
    sc_kernel<<<N, 288>>>(nf, Wsc0, Wsc1, Wsc2, out);
    msg_kernel<<<(E + TEDGE - 1) / TEDGE, NTHR, SMEM>>>(nf, ei, sh, out, E);
}

// round 10
// speedup vs baseline: 11.7457x; 1.0057x over previous
#include <cuda_runtime.h>
#include <cuda_fp16.h>
#include <math.h>
#include <stdint.h>

#define NTHR 512
#define TEDGE 64
#define EPAD 65

// ---------------- device scratch (static, no allocation) ----------------
__device__ float g_w3j[11 * 125];        // per-instruction wigner3j, pre-scaled by PW[l3]
__device__ uint4 g_W2H[11 * 32 * 4 * 2 * 32];  // W2 in fp16 B-fragment layout (1.44 MB)
__device__ __half g_Hh[20000 * 64];      // weight-NN hidden activations (fp16)
__device__ float g_agg[2048 * 288];      // message aggregation buffer (zeroed by final_kernel)

// irrep constants
constexpr int DIMS_[3] = {1, 3, 5};
constexpr int OFF_[3]  = {0, 32, 128};  // offsets into 288-dim feature
constexpr int SO_[3]   = {0, 1, 4};     // offsets into 9-dim sh
constexpr int KO_[3]   = {0, 1, 4};     // offsets into 9-slot accumulator

// fp16 m16n8k16 MMA, D += A*B (fp32 accumulate)
__device__ __forceinline__ void mma_f16(float* d, const uint32_t* a, uint32_t b0, uint32_t b1) {
    asm volatile(
        "mma.sync.aligned.m16n8k16.row.col.f32.f16.f16.f32 "
        "{%0,%1,%2,%3}, {%4,%5,%6,%7}, {%8,%9}, {%0,%1,%2,%3};\n"
        : "+f"(d[0]), "+f"(d[1]), "+f"(d[2]), "+f"(d[3])
        : "r"(a[0]), "r"(a[1]), "r"(a[2]), "r"(a[3]), "r"(b0), "r"(b1));
}

// ======================= wigner-3j setup (reference algorithm) =======================
__device__ __forceinline__ double dfact(int n) {
    double r = 1.0;
    for (int i = 2; i <= n; i++) r *= (double)i;
    return r;
}

__device__ void build_q(int l, double* qr, double* qi) {
    int D = 2 * l + 1;
    for (int i = 0; i < D * D; i++) { qr[i] = 0.0; qi[i] = 0.0; }
    const double s2 = 0.70710678118654752440;
    for (int m = -l; m < 0; m++) {
        qr[(l + m) * D + (l - m)] = s2;
        qi[(l + m) * D + (l + m)] = -s2;
    }
    qr[l * D + l] = 1.0;
    for (int m = 1; m <= l; m++) {
        double sg = (m & 1) ? -1.0 : 1.0;
        qr[(l + m) * D + (l + m)] = sg * s2;
        qi[(l + m) * D + (l - m)] = sg * s2;
    }
    double fr, fi;
    switch (l & 3) {
        case 0: fr = 1;  fi = 0;  break;
        case 1: fr = 0;  fi = -1; break;
        case 2: fr = -1; fi = 0;  break;
        default: fr = 0; fi = 1;  break;
    }
    for (int i = 0; i < D * D; i++) {
        double r = qr[i], im = qi[i];
        qr[i] = r * fr - im * fi;
        qi[i] = r * fi + im * fr;
    }
}

__global__ void w3j_setup_kernel() {
    const int L1[11] = {0, 0, 0, 1, 1, 1, 1, 2, 2, 2, 2};
    const int L2[11] = {0, 1, 2, 0, 1, 1, 2, 0, 1, 2, 2};
    const int L3[11] = {0, 1, 2, 1, 0, 2, 1, 2, 1, 0, 2};
    int t = blockIdx.x;
    int j1 = L1[t], j2 = L2[t], j3 = L3[t];
    int d1 = 2 * j1 + 1, d2 = 2 * j2 + 1, d3 = 2 * j3 + 1;
    __shared__ double Cs[125];
    __shared__ double Q1r[25], Q1i[25], Q2r[25], Q2i[25], Q3r[25], Q3i[25];
    __shared__ double outv[125];
    __shared__ double scale_s;
    int tid = threadIdx.x;
    if (tid < 125) Cs[tid] = 0.0;
    if (tid == 0) {
        build_q(j1, Q1r, Q1i);
        build_q(j2, Q2r, Q2i);
        build_q(j3, Q3r, Q3i);
    }
    __syncthreads();
    if (tid < d1 * d2) {
        int m1 = tid / d2 - j1;
        int m2 = tid % d2 - j2;
        int m3 = m1 + m2;
        if (m3 >= -j3 && m3 <= j3) {
            int vmin = -j1 + j2 + m3;
            if (-j1 + m1 > vmin) vmin = -j1 + m1;
            if (vmin < 0) vmin = 0;
            int vmax = j2 + j3 + m1;
            if (j3 - j1 + j2 < vmax) vmax = j3 - j1 + j2;
            if (j3 + m3 < vmax) vmax = j3 + m3;
            double c = sqrt((double)(2 * j3 + 1) * dfact(j3 + j1 - j2) * dfact(j3 - j1 + j2) *
                            dfact(j1 + j2 - j3) * dfact(j3 + m3) * dfact(j3 - m3) /
                            (dfact(j1 + j2 + j3 + 1) * dfact(j1 - m1) * dfact(j1 + m1) *
                             dfact(j2 - m2) * dfact(j2 + m2)));
            double s = 0.0;
            for (int v = vmin; v <= vmax; v++) {
                double term = dfact(j2 + j3 + m1 - v) * dfact(j1 - m1 + v) /
                              (dfact(v) * dfact(j3 - j1 + j2 - v) * dfact(j3 + m3 - v) *
                               dfact(v + j1 - j2 - m3));
                if ((v + j2 + m2) & 1) term = -term;
                s += term;
            }
            Cs[((m1 + j1) * d2 + (m2 + j2)) * d3 + (m3 + j3)] = c * s;
        }
    }
    __syncthreads();
    int nel = d1 * d2 * d3;
    if (tid < nel) {
        int jj = tid / (d2 * d3);
        int ll = (tid / d3) % d2;
        int mm = tid % d3;
        double ar = 0.0;
        for (int i = 0; i < d1; i++)
            for (int k = 0; k < d2; k++)
                for (int n = 0; n < d3; n++) {
                    double cv = Cs[(i * d2 + k) * d3 + n];
                    if (cv == 0.0) continue;
                    double p1r = Q1r[i * d1 + jj], p1i = Q1i[i * d1 + jj];
                    double p2r = Q2r[k * d2 + ll], p2i = Q2i[k * d2 + ll];
                    double p3r = Q3r[n * d3 + mm], p3i = -Q3i[n * d3 + mm];
                    double t1r = p1r * p2r - p1i * p2i;
                    double t1i = p1r * p2i + p1i * p2r;
                    double t2r = t1r * p3r - t1i * p3i;
                    ar += t2r * cv;
                }
        outv[tid] = ar;
    }
    __syncthreads();
    if (tid == 0) {
        const double PWv[3] = {0.10206207261596575, 0.15309310892394862, 0.19764235376052370};
        double s = 0.0;
        for (int i = 0; i < nel; i++) s += outv[i] * outv[i];
        scale_s = PWv[j3] / sqrt(s);
    }
    __syncthreads();
    if (tid < nel) g_w3j[t * 125 + tid] = (float)(outv[tid] * scale_s);
}

// ======================= W2 relayout into fp16 B-fragment order =======================
__global__ void w2h_kernel(const float* __restrict__ W2) {
    int idx = blockIdx.x * 256 + threadIdx.x;
    if (idx >= 64 * 11264) return;
    int c = idx / 11264;
    int col = idx - c * 11264;
    int ins = col >> 10;
    int rem = col & 1023;
    int u = rem >> 5;
    int w = rem & 31;
    int wtile = w >> 3, n = w & 7;
    int q = c >> 4, cl = c & 15;
    int hsel = cl >> 3;
    int c8 = cl & 7;
    int tig = c8 >> 1, pp = c8 & 1;
    int lane = (n << 2) | tig;
    int q2 = q >> 1, qq = q & 1;
    int u4 = (((ins * 32 + u) * 4 + wtile) * 2 + q2) * 32 + lane;
    int hidx = u4 * 8 + (qq * 2 + hsel) * 2 + pp;
    ((__half*)g_W2H)[hidx] = __float2half(W2[idx] * 0.125f);
}

// ======================= weight-NN hidden layer (fp16 output) =======================
__global__ void h_kernel(const float* __restrict__ radial, const float* __restrict__ W1,
                         float cst, int E) {
    __shared__ float rs[4][64];
    int le = threadIdx.x >> 6, c = threadIdx.x & 63;
    int e = blockIdx.x * 4 + le;
    rs[le][c] = (e < E) ? radial[e * 64 + c] : 0.f;
    __syncthreads();
    float a = 0.f;
#pragma unroll
    for (int r = 0; r < 64; r++) a += rs[le][r] * W1[r * 64 + c];
    a *= 0.125f;  // 1/sqrt(64)
    float hv = cst * a / (1.f + expf(-a));
    if (e < E) g_Hh[e * 64 + c] = __float2half(hv);
}

// ======================= fused message kernel (pipelined, fp16 MMA) =======================
// Block = 512 threads = 16 warps, 64 edges. Warp wid: wtile = wid&3, rtile = wid>>2.
// Software pipeline: compute_z(ins i+1) overlaps mma_phase(ins i); zs double-buffered.

// z computation with fused s: thread owns fixed edge e = tid&63, u = (tid>>6) + s*8.
template <int D1, int D2, int D3, int SO2, int O1, int W3OFF>
__device__ __forceinline__ void compute_z(const float* __restrict__ xs,
                                          float* __restrict__ zb,
                                          const float* __restrict__ shT,
                                          const float* __restrict__ w3j_s, int tid) {
    int e = tid & 63;
    int u0 = tid >> 6;  // 0..7
    float shv[D2];
#pragma unroll
    for (int j = 0; j < D2; j++) shv[j] = shT[(SO2 + j) * EPAD + e];
    float sv[D1 * D3];
#pragma unroll
    for (int i = 0; i < D1; i++)
#pragma unroll
        for (int k = 0; k < D3; k++) {
            float a = 0.f;
#pragma unroll
            for (int j = 0; j < D2; j++)
                a += w3j_s[W3OFF + (i * D2 + j) * D3 + k] * shv[j];
            sv[i * D3 + k] = a;
        }
#pragma unroll
    for (int s = 0; s < 4; s++) {
        int u = u0 + s * 8;
        float xv[D1];
#pragma unroll
        for (int i = 0; i < D1; i++) xv[i] = xs[(O1 + u * D1 + i) * EPAD + e];
#pragma unroll
        for (int k = 0; k < D3; k++) {
            float z = 0.f;
#pragma unroll
            for (int i = 0; i < D1; i++) z += xv[i] * sv[i * D3 + k];
            zb[(u * D3 + k) * EPAD + e] = z;
        }
    }
}

// MMA + consume phase for one ins, depth-2 B prefetch.
template <int D3, int KO, int PB>
__device__ __forceinline__ void mma_phase(const float* __restrict__ zb,
                                          const uint32_t (&af)[4][4], float (&acc)[4][9],
                                          int lane, int wtile, int er0, int er1) {
    const uint4* __restrict__ Bp = g_W2H + PB + wtile * 64 + lane;
    uint4 Bc0 = __ldg(Bp),       Bc1 = __ldg(Bp + 32);         // u=0
    uint4 Bd0 = __ldg(Bp + 256), Bd1 = __ldg(Bp + 288);        // u=1
#pragma unroll 1
    for (int u = 0; u < 32; u++) {
        uint4 Be0, Be1;
        if (u < 30) {
            const uint4* __restrict__ Bu = Bp + (u + 2) * 256;
            Be0 = __ldg(Bu);
            Be1 = __ldg(Bu + 32);
        }
        float c0[4] = {0.f, 0.f, 0.f, 0.f};
        float c1[4] = {0.f, 0.f, 0.f, 0.f};
        mma_f16(c0, af[0], Bc0.x, Bc0.y);
        mma_f16(c1, af[1], Bc0.z, Bc0.w);
        mma_f16(c0, af[2], Bc1.x, Bc1.y);
        mma_f16(c1, af[3], Bc1.z, Bc1.w);
        float wv0 = c0[0] + c1[0];
        float wv1 = c0[1] + c1[1];
        float wv2 = c0[2] + c1[2];
        float wv3 = c0[3] + c1[3];
#pragma unroll
        for (int k = 0; k < D3; k++) {
            float z0 = zb[(u * D3 + k) * EPAD + er0];
            float z1 = zb[(u * D3 + k) * EPAD + er1];
            acc[0][KO + k] += wv0 * z0;
            acc[1][KO + k] += wv1 * z0;
            acc[2][KO + k] += wv2 * z1;
            acc[3][KO + k] += wv3 * z1;
        }
        Bc0 = Bd0; Bc1 = Bd1;
        Bd0 = Be0; Bd1 = Be1;
    }
}

// per-ins template args: A=i1, B=i2, C=i3
#define CZ(IDX, A, B, Cc, BUF)                                                          \
    compute_z<DIMS_[A], DIMS_[B], DIMS_[Cc], SO_[B], OFF_[A], IDX * 125>(               \
        xs, BUF, shT, w3j_s, tid)
#define MP(IDX, A, B, Cc, BUF)                                                          \
    mma_phase<DIMS_[Cc], KO_[Cc], IDX * 8192>(BUF, af, acc, lane, wtile, er0, er1)

__global__ void __launch_bounds__(NTHR, 1)
msg_kernel(const float* __restrict__ nf, const int* __restrict__ ei,
           const float* __restrict__ shg, int E) {
    extern __shared__ float smem[];
    float* xs    = smem;                          // 288*65
    __half* hsm  = (__half*)(xs + 288 * EPAD);    // 64*64 halves (2048 floats)
    float* zb0   = xs + 288 * EPAD + TEDGE * 32;  // 32*5*65
    float* zb1   = zb0 + 32 * 5 * EPAD;           // 32*5*65
    float* shT   = zb1 + 32 * 5 * EPAD;           // 9*65
    float* w3j_s = shT + 9 * EPAD;                // 1375
    int* srcdst  = (int*)(w3j_s + 1375);          // 128 ints
    int tid = threadIdx.x;
    int e0 = blockIdx.x * TEDGE;

    if (tid < 128) {
        int e = e0 + (tid & 63);
        int which = tid >> 6;
        srcdst[tid] = (e < E) ? ei[which * E + e] : 0;
    }
    __syncthreads();
    for (int idx = tid; idx < TEDGE * 288; idx += NTHR) {
        int e = idx / 288;
        int c = idx - e * 288;
        xs[c * EPAD + e] = (e0 + e < E) ? nf[srcdst[e] * 288 + c] : 0.f;
    }
    for (int idx = tid; idx < TEDGE * 64; idx += NTHR) {
        int e = idx >> 6;
        int c = idx & 63;
        hsm[e * 64 + c] = (e0 + e < E) ? g_Hh[(e0 + e) * 64 + c] : __float2half(0.f);
    }
    for (int idx = tid; idx < TEDGE * 9; idx += NTHR) {
        int e = idx & 63;
        int j = idx >> 6;
        shT[j * EPAD + e] = (e0 + e < E) ? shg[(e0 + e) * 9 + j] : 0.f;
    }
    for (int idx = tid; idx < 11 * 125; idx += NTHR) w3j_s[idx] = g_w3j[idx];
    __syncthreads();

    int lane = tid & 31;
    int wid = tid >> 5;
    int rtile = wid >> 2, wtile = wid & 3;
    int g = lane >> 2, tig = lane & 3;
    int er0 = rtile * 16 + g, er1 = er0 + 8;
    int wc0 = wtile * 8 + 2 * tig, wc1 = wc0 + 1;

    // A fragments (h, fp16 half2-packed), resident all kernel.
    const uint32_t* hs2 = (const uint32_t*)hsm;
    uint32_t af[4][4];
#pragma unroll
    for (int q = 0; q < 4; q++) {
        af[q][0] = hs2[er0 * 32 + q * 8 + tig];
        af[q][1] = hs2[er1 * 32 + q * 8 + tig];
        af[q][2] = hs2[er0 * 32 + q * 8 + 4 + tig];
        af[q][3] = hs2[er1 * 32 + q * 8 + 4 + tig];
    }

    float acc[4][9];
#pragma unroll
    for (int p = 0; p < 4; p++)
#pragma unroll
        for (int k = 0; k < 9; k++) acc[p][k] = 0.f;

    // Software pipeline: z(i) in buf(i&1); iter i: write z(i+1), mma(i), barrier.
    CZ(0, 0, 0, 0, zb0);
    __syncthreads();
    CZ(1, 0, 1, 1, zb1);   MP(0, 0, 0, 0, zb0);  __syncthreads();
    CZ(2, 0, 2, 2, zb0);   MP(1, 0, 1, 1, zb1);  __syncthreads();
    CZ(3, 1, 0, 1, zb1);   MP(2, 0, 2, 2, zb0);  __syncthreads();
    CZ(4, 1, 1, 0, zb0);   MP(3, 1, 0, 1, zb1);  __syncthreads();
    CZ(5, 1, 1, 2, zb1);   MP(4, 1, 1, 0, zb0);  __syncthreads();
    CZ(6, 1, 2, 1, zb0);   MP(5, 1, 1, 2, zb1);  __syncthreads();
    CZ(7, 2, 0, 2, zb1);   MP(6, 1, 2, 1, zb0);  __syncthreads();
    CZ(8, 2, 1, 1, zb0);   MP(7, 2, 0, 2, zb1);  __syncthreads();
    CZ(9, 2, 2, 0, zb1);   MP(8, 2, 1, 1, zb0);  __syncthreads();
    CZ(10, 2, 2, 2, zb0);  MP(9, 2, 2, 0, zb1);  __syncthreads();
    MP(10, 2, 2, 2, zb0);

    // Raw accumulation into g_agg (final_kernel applies 1/sqrt(10) and adds self-connection).
#pragma unroll
    for (int p = 0; p < 4; p++) {
        int e = (p & 2) ? er1 : er0;
        int wcol = (p & 1) ? wc1 : wc0;
        if (e0 + e >= E) continue;
        int node = srcdst[64 + e];
        float* op = g_agg + node * 288;
        float* ac = acc[p];
        atomicAdd(op + wcol, ac[0]);
#pragma unroll
        for (int k = 0; k < 3; k++) atomicAdd(op + 32 + wcol * 3 + k, ac[1 + k]);
#pragma unroll
        for (int k = 0; k < 5; k++) atomicAdd(op + 128 + wcol * 5 + k, ac[4 + k]);
    }
}

// ======================= final: out = agg/sqrt(10) + self-connection; re-zero agg ==========
__global__ void final_kernel(const float* __restrict__ nf, const float* __restrict__ w0,
                             const float* __restrict__ w1, const float* __restrict__ w2,
                             float* __restrict__ out) {
    __shared__ float xrow[288];
    int n = blockIdx.x;
    int t = threadIdx.x;
    xrow[t] = nf[n * 288 + t];
    __syncthreads();
    int O, d, wch, k;
    const float* W;
    if (t < 32)       { O = 0;   d = 1; wch = t;          k = 0;            W = w0; }
    else if (t < 128) { int r = t - 32;  O = 32;  d = 3; wch = r / 3; k = r - wch * 3; W = w1; }
    else              { int r = t - 128; O = 128; d = 5; wch = r / 5; k = r - wch * 5; W = w2; }
    float a = 0.f;
#pragma unroll
    for (int u = 0; u < 32; u++) a += xrow[O + u * d + k] * W[u * 32 + wch];
    int oidx = n * 288 + t;
    float agg = g_agg[oidx];
    g_agg[oidx] = 0.f;  // reset for next graph replay
    out[oidx] = agg * 0.31622776601683794f + a * 0.17677669529663687f;
}

// ======================= host: numpy RandomState(0) SILU_CST reproduction =======================
namespace {
struct NpRng {
    uint32_t mt[624];
    int mti;
    bool has_g;
    double g;
};
inline void rng_seed(NpRng& s, uint32_t sd) {
    s.mt[0] = sd;
    for (int i = 1; i < 624; i++)
        s.mt[i] = 1812433253u * (s.mt[i - 1] ^ (s.mt[i - 1] >> 30)) + (uint32_t)i;
    s.mti = 624;
    s.has_g = false;
    s.g = 0.0;
}
inline uint32_t rng_u32(NpRng& s) {
    if (s.mti >= 624) {
        for (int i = 0; i < 624; i++) {
            uint32_t y = (s.mt[i] & 0x80000000u) | (s.mt[(i + 1) % 624] & 0x7fffffffu);
            s.mt[i] = s.mt[(i + 397) % 624] ^ (y >> 1) ^ ((y & 1u) ? 0x9908b0dfu : 0u);
        }
        s.mti = 0;
    }
    uint32_t y = s.mt[s.mti++];
    y ^= y >> 11;
    y ^= (y << 7) & 0x9d2c5680u;
    y ^= (y << 15) & 0xefc60000u;
    y ^= y >> 18;
    return y;
}
inline double rng_double(NpRng& s) {
    uint32_t a = rng_u32(s) >> 5;
    uint32_t b = rng_u32(s) >> 6;
    return ((double)a * 67108864.0 + (double)b) / 9007199254740992.0;
}
inline double rng_gauss(NpRng& s) {
    if (s.has_g) {
        s.has_g = false;
        return s.g;
    }
    double x1, x2, r2;
    do {
        x1 = 2.0 * rng_double(s) - 1.0;
        x2 = 2.0 * rng_double(s) - 1.0;
        r2 = x1 * x1 + x2 * x2;
    } while (r2 >= 1.0 || r2 == 0.0);
    double f = sqrt(-2.0 * log(r2) / r2);
    s.g = f * x1;
    s.has_g = true;
    return f * x2;
}
inline double compute_silu_cst() {
    NpRng s;
    rng_seed(s, 0u);
    double sum = 0.0;
    for (int i = 0; i < 1000000; i++) {
        double z = rng_gauss(s);
        double sl = z / (1.0 + exp(-z));
        sum += sl * sl;
    }
    return 1.0 / sqrt(sum / 1000000.0);
}
}  // namespace

// ======================= launch =======================
extern "C" void kernel_launch(void* const* d_in, const int* in_sizes, int n_in,
                              void* d_out, int out_size) {
    const float* nf     = (const float*)d_in[0];
    const int*   ei     = (const int*)d_in[1];
    const float* sh     = (const float*)d_in[2];
    const float* radial = (const float*)d_in[3];
    const float* W1     = (const float*)d_in[4];
    const float* W2     = (const float*)d_in[5];
    const float* Wsc0   = (const float*)d_in[6];
    const float* Wsc1   = (const float*)d_in[7];
    const float* Wsc2   = (const float*)d_in[8];
    float* out = (float*)d_out;
    int N = in_sizes[0] / 288;
    int E = in_sizes[1] / 2;

    float cst = (float)compute_silu_cst();

    const size_t SMEM = (288 * EPAD + TEDGE * 32 + 2 * 32 * 5 * EPAD + 9 * EPAD + 1375) * 4
                        + 128 * 4;  // ~175 KB
    cudaFuncSetAttribute(msg_kernel, cudaFuncAttributeMaxDynamicSharedMemorySize, (int)SMEM);

    w3j_setup_kernel<<<11, 128>>>();
    w2h_kernel<<<(64 * 11264 + 255) / 256, 256>>>(W2);
    h_kernel<<<(E + 3) / 4, 256>>>(radial, W1, cst, E);
    msg_kernel<<<(E + TEDGE - 1) / TEDGE, NTHR, SMEM>>>(nf, ei, sh, E);
    final_kernel<<<N, 288>>>(nf, Wsc0, Wsc1, Wsc2, out);
}

// round 12
// speedup vs baseline: 16.0516x; 1.3666x over previous
#include <cuda_runtime.h>
#include <cuda_fp16.h>
#include <math.h>
#include <stdint.h>

#define NTHR 512
#define TEDGE 64
#define EPAD 65

// ---------------- device scratch (static, no allocation) ----------------
__device__ float g_w3j[11 * 125];        // per-instruction wigner3j, pre-scaled by PW[l3]
__device__ uint4 g_W2H[11 * 32 * 4 * 2 * 32];  // W2 in fp16 B-fragment layout (1.44 MB)
__device__ __half g_Hh[20000 * 64];      // weight-NN hidden activations (fp16)
__device__ float g_agg[2048 * 288];      // message aggregation buffer (zeroed by final_kernel)

// irrep constants
constexpr int DIMS_[3] = {1, 3, 5};
constexpr int OFF_[3]  = {0, 32, 128};  // offsets into 288-dim feature
constexpr int SO_[3]   = {0, 1, 4};     // offsets into 9-dim sh
constexpr int KO_[3]   = {0, 1, 4};     // offsets into 9-slot accumulator

// fp16 m16n8k16 MMA, D += A*B (fp32 accumulate)
__device__ __forceinline__ void mma_f16(float* d, const uint32_t* a, uint32_t b0, uint32_t b1) {
    asm volatile(
        "mma.sync.aligned.m16n8k16.row.col.f32.f16.f16.f32 "
        "{%0,%1,%2,%3}, {%4,%5,%6,%7}, {%8,%9}, {%0,%1,%2,%3};\n"
        : "+f"(d[0]), "+f"(d[1]), "+f"(d[2]), "+f"(d[3])
        : "r"(a[0]), "r"(a[1]), "r"(a[2]), "r"(a[3]), "r"(b0), "r"(b1));
}

// ======================= wigner-3j setup (reference algorithm) =======================
__device__ __forceinline__ double dfact(int n) {
    double r = 1.0;
    for (int i = 2; i <= n; i++) r *= (double)i;
    return r;
}

__device__ void build_q(int l, double* qr, double* qi) {
    int D = 2 * l + 1;
    for (int i = 0; i < D * D; i++) { qr[i] = 0.0; qi[i] = 0.0; }
    const double s2 = 0.70710678118654752440;
    for (int m = -l; m < 0; m++) {
        qr[(l + m) * D + (l - m)] = s2;
        qi[(l + m) * D + (l + m)] = -s2;
    }
    qr[l * D + l] = 1.0;
    for (int m = 1; m <= l; m++) {
        double sg = (m & 1) ? -1.0 : 1.0;
        qr[(l + m) * D + (l + m)] = sg * s2;
        qi[(l + m) * D + (l - m)] = sg * s2;
    }
    double fr, fi;
    switch (l & 3) {
        case 0: fr = 1;  fi = 0;  break;
        case 1: fr = 0;  fi = -1; break;
        case 2: fr = -1; fi = 0;  break;
        default: fr = 0; fi = 1;  break;
    }
    for (int i = 0; i < D * D; i++) {
        double r = qr[i], im = qi[i];
        qr[i] = r * fr - im * fi;
        qi[i] = r * fi + im * fr;
    }
}

__global__ void w3j_setup_kernel() {
    const int L1[11] = {0, 0, 0, 1, 1, 1, 1, 2, 2, 2, 2};
    const int L2[11] = {0, 1, 2, 0, 1, 1, 2, 0, 1, 2, 2};
    const int L3[11] = {0, 1, 2, 1, 0, 2, 1, 2, 1, 0, 2};
    int t = blockIdx.x;
    int j1 = L1[t], j2 = L2[t], j3 = L3[t];
    int d1 = 2 * j1 + 1, d2 = 2 * j2 + 1, d3 = 2 * j3 + 1;
    __shared__ double Cs[125];
    __shared__ double Q1r[25], Q1i[25], Q2r[25], Q2i[25], Q3r[25], Q3i[25];
    __shared__ double outv[125];
    __shared__ double scale_s;
    int tid = threadIdx.x;
    if (tid < 125) Cs[tid] = 0.0;
    if (tid == 0) {
        build_q(j1, Q1r, Q1i);
        build_q(j2, Q2r, Q2i);
        build_q(j3, Q3r, Q3i);
    }
    __syncthreads();
    if (tid < d1 * d2) {
        int m1 = tid / d2 - j1;
        int m2 = tid % d2 - j2;
        int m3 = m1 + m2;
        if (m3 >= -j3 && m3 <= j3) {
            int vmin = -j1 + j2 + m3;
            if (-j1 + m1 > vmin) vmin = -j1 + m1;
            if (vmin < 0) vmin = 0;
            int vmax = j2 + j3 + m1;
            if (j3 - j1 + j2 < vmax) vmax = j3 - j1 + j2;
            if (j3 + m3 < vmax) vmax = j3 + m3;
            double c = sqrt((double)(2 * j3 + 1) * dfact(j3 + j1 - j2) * dfact(j3 - j1 + j2) *
                            dfact(j1 + j2 - j3) * dfact(j3 + m3) * dfact(j3 - m3) /
                            (dfact(j1 + j2 + j3 + 1) * dfact(j1 - m1) * dfact(j1 + m1) *
                             dfact(j2 - m2) * dfact(j2 + m2)));
            double s = 0.0;
            for (int v = vmin; v <= vmax; v++) {
                double term = dfact(j2 + j3 + m1 - v) * dfact(j1 - m1 + v) /
                              (dfact(v) * dfact(j3 - j1 + j2 - v) * dfact(j3 + m3 - v) *
                               dfact(v + j1 - j2 - m3));
                if ((v + j2 + m2) & 1) term = -term;
                s += term;
            }
            Cs[((m1 + j1) * d2 + (m2 + j2)) * d3 + (m3 + j3)] = c * s;
        }
    }
    __syncthreads();
    int nel = d1 * d2 * d3;
    if (tid < nel) {
        int jj = tid / (d2 * d3);
        int ll = (tid / d3) % d2;
        int mm = tid % d3;
        double ar = 0.0;
        for (int i = 0; i < d1; i++)
            for (int k = 0; k < d2; k++)
                for (int n = 0; n < d3; n++) {
                    double cv = Cs[(i * d2 + k) * d3 + n];
                    if (cv == 0.0) continue;
                    double p1r = Q1r[i * d1 + jj], p1i = Q1i[i * d1 + jj];
                    double p2r = Q2r[k * d2 + ll], p2i = Q2i[k * d2 + ll];
                    double p3r = Q3r[n * d3 + mm], p3i = -Q3i[n * d3 + mm];
                    double t1r = p1r * p2r - p1i * p2i;
                    double t1i = p1r * p2i + p1i * p2r;
                    double t2r = t1r * p3r - t1i * p3i;
                    ar += t2r * cv;
                }
        outv[tid] = ar;
    }
    __syncthreads();
    if (tid == 0) {
        const double PWv[3] = {0.10206207261596575, 0.15309310892394862, 0.19764235376052370};
        double s = 0.0;
        for (int i = 0; i < nel; i++) s += outv[i] * outv[i];
        scale_s = PWv[j3] / sqrt(s);
    }
    __syncthreads();
    if (tid < nel) g_w3j[t * 125 + tid] = (float)(outv[tid] * scale_s);
}

// ======================= W2 relayout into fp16 B-fragment order =======================
__global__ void w2h_kernel(const float* __restrict__ W2) {
    int idx = blockIdx.x * 256 + threadIdx.x;
    if (idx >= 64 * 11264) return;
    int c = idx / 11264;
    int col = idx - c * 11264;
    int ins = col >> 10;
    int rem = col & 1023;
    int u = rem >> 5;
    int w = rem & 31;
    int wtile = w >> 3, n = w & 7;
    int q = c >> 4, cl = c & 15;
    int hsel = cl >> 3;
    int c8 = cl & 7;
    int tig = c8 >> 1, pp = c8 & 1;
    int lane = (n << 2) | tig;
    int q2 = q >> 1, qq = q & 1;
    int u4 = (((ins * 32 + u) * 4 + wtile) * 2 + q2) * 32 + lane;
    int hidx = u4 * 8 + (qq * 2 + hsel) * 2 + pp;
    ((__half*)g_W2H)[hidx] = __float2half(W2[idx] * 0.125f);
}

// ======================= weight-NN hidden layer (fp16 output) =======================
__global__ void h_kernel(const float* __restrict__ radial, const float* __restrict__ W1,
                         float cst, int E) {
    __shared__ float rs[4][64];
    int le = threadIdx.x >> 6, c = threadIdx.x & 63;
    int e = blockIdx.x * 4 + le;
    rs[le][c] = (e < E) ? radial[e * 64 + c] : 0.f;
    __syncthreads();
    float a = 0.f;
#pragma unroll
    for (int r = 0; r < 64; r++) a += rs[le][r] * W1[r * 64 + c];
    a *= 0.125f;  // 1/sqrt(64)
    float hv = cst * a / (1.f + expf(-a));
    if (e < E) g_Hh[e * 64 + c] = __float2half(hv);
}

// ======================= fused message kernel (persistent, pipelined, fp16 MMA) ==========
// Block = 512 threads = 16 warps, 64 edges per tile. Warp wid: wtile = wid&3, rtile = wid>>2.
// Persistent: grid = min(296, ntiles); block processes tiles blockIdx.x, +gridDim.x, ...

// z computation with fused s: thread owns fixed edge e = tid&63, u = (tid>>6) + s*8.
template <int D1, int D2, int D3, int SO2, int O1, int W3OFF>
__device__ __forceinline__ void compute_z(const float* __restrict__ xs,
                                          float* __restrict__ zb,
                                          const float* __restrict__ shT,
                                          const float* __restrict__ w3j_s, int tid) {
    int e = tid & 63;
    int u0 = tid >> 6;  // 0..7
    float shv[D2];
#pragma unroll
    for (int j = 0; j < D2; j++) shv[j] = shT[(SO2 + j) * EPAD + e];
    float sv[D1 * D3];
#pragma unroll
    for (int i = 0; i < D1; i++)
#pragma unroll
        for (int k = 0; k < D3; k++) {
            float a = 0.f;
#pragma unroll
            for (int j = 0; j < D2; j++)
                a += w3j_s[W3OFF + (i * D2 + j) * D3 + k] * shv[j];
            sv[i * D3 + k] = a;
        }
#pragma unroll
    for (int s = 0; s < 4; s++) {
        int u = u0 + s * 8;
        float xv[D1];
#pragma unroll
        for (int i = 0; i < D1; i++) xv[i] = xs[(O1 + u * D1 + i) * EPAD + e];
#pragma unroll
        for (int k = 0; k < D3; k++) {
            float z = 0.f;
#pragma unroll
            for (int i = 0; i < D1; i++) z += xv[i] * sv[i * D3 + k];
            zb[(u * D3 + k) * EPAD + e] = z;
        }
    }
}

// Consume one u: 4 MMAs (2 independent chains) + z-weighted accumulation.
template <int D3, int KO>
__device__ __forceinline__ void consume_u(const float* __restrict__ zb,
                                          const uint32_t (&af)[4][4], float (&acc)[4][9],
                                          int u, int er0, int er1,
                                          const uint4& Ba, const uint4& Bb) {
    float c0[4] = {0.f, 0.f, 0.f, 0.f};
    float c1[4] = {0.f, 0.f, 0.f, 0.f};
    mma_f16(c0, af[0], Ba.x, Ba.y);
    mma_f16(c1, af[1], Ba.z, Ba.w);
    mma_f16(c0, af[2], Bb.x, Bb.y);
    mma_f16(c1, af[3], Bb.z, Bb.w);
    float wv0 = c0[0] + c1[0];
    float wv1 = c0[1] + c1[1];
    float wv2 = c0[2] + c1[2];
    float wv3 = c0[3] + c1[3];
#pragma unroll
    for (int k = 0; k < D3; k++) {
        float z0 = zb[(u * D3 + k) * EPAD + er0];
        float z1 = zb[(u * D3 + k) * EPAD + er1];
        acc[0][KO + k] += wv0 * z0;
        acc[1][KO + k] += wv1 * z0;
        acc[2][KO + k] += wv2 * z1;
        acc[3][KO + k] += wv3 * z1;
    }
}

// MMA phase for one ins: unroll-4 register rotation, depth-4 B prefetch (covers L2 latency).
template <int D3, int KO, int PB>
__device__ __forceinline__ void mma_phase(const float* __restrict__ zb,
                                          const uint32_t (&af)[4][4], float (&acc)[4][9],
                                          int lane, int wtile, int er0, int er1) {
    const uint4* __restrict__ Bp = g_W2H + PB + wtile * 64 + lane;
    uint4 s0a = __ldg(Bp +   0), s0b = __ldg(Bp +  32);   // u=0
    uint4 s1a = __ldg(Bp + 256), s1b = __ldg(Bp + 288);   // u=1
    uint4 s2a = __ldg(Bp + 512), s2b = __ldg(Bp + 544);   // u=2
    uint4 s3a = __ldg(Bp + 768), s3b = __ldg(Bp + 800);   // u=3
#pragma unroll 1
    for (int ub = 0; ub < 32; ub += 4) {
        bool more = ub < 28;
        consume_u<D3, KO>(zb, af, acc, ub + 0, er0, er1, s0a, s0b);
        if (more) { const uint4* B = Bp + (ub + 4) * 256; s0a = __ldg(B); s0b = __ldg(B + 32); }
        consume_u<D3, KO>(zb, af, acc, ub + 1, er0, er1, s1a, s1b);
        if (more) { const uint4* B = Bp + (ub + 5) * 256; s1a = __ldg(B); s1b = __ldg(B + 32); }
        consume_u<D3, KO>(zb, af, acc, ub + 2, er0, er1, s2a, s2b);
        if (more) { const uint4* B = Bp + (ub + 6) * 256; s2a = __ldg(B); s2b = __ldg(B + 32); }
        consume_u<D3, KO>(zb, af, acc, ub + 3, er0, er1, s3a, s3b);
        if (more) { const uint4* B = Bp + (ub + 7) * 256; s3a = __ldg(B); s3b = __ldg(B + 32); }
    }
}

// per-ins template args: A=i1, B=i2, C=i3
#define CZ(IDX, A, B, Cc, BUF)                                                          \
    compute_z<DIMS_[A], DIMS_[B], DIMS_[Cc], SO_[B], OFF_[A], IDX * 125>(               \
        xs, BUF, shT, w3j_s, tid)
#define MP(IDX, A, B, Cc, BUF)                                                          \
    mma_phase<DIMS_[Cc], KO_[Cc], IDX * 8192>(BUF, af, acc, lane, wtile, er0, er1)

__global__ void __launch_bounds__(NTHR, 1)
msg_kernel(const float* __restrict__ nf, const int* __restrict__ ei,
           const float* __restrict__ shg, int E, int ntiles) {
    extern __shared__ float smem[];
    float* xs    = smem;                          // 288*65
    __half* hsm  = (__half*)(xs + 288 * EPAD);    // 64*64 halves (2048 floats)
    float* zb0   = xs + 288 * EPAD + TEDGE * 32;  // 32*5*65
    float* zb1   = zb0 + 32 * 5 * EPAD;           // 32*5*65
    float* shT   = zb1 + 32 * 5 * EPAD;           // 9*65
    float* w3j_s = shT + 9 * EPAD;                // 1375
    int* srcdst  = (int*)(w3j_s + 1375);          // 128 ints
    int tid = threadIdx.x;

    // loop-invariant: w3j table (visibility covered by loop-top barrier)
    for (int idx = tid; idx < 11 * 125; idx += NTHR) w3j_s[idx] = g_w3j[idx];

    int lane = tid & 31;
    int wid = tid >> 5;
    int rtile = wid >> 2, wtile = wid & 3;
    int g = lane >> 2, tig = lane & 3;
    int er0 = rtile * 16 + g, er1 = er0 + 8;
    int wc0 = wtile * 8 + 2 * tig, wc1 = wc0 + 1;
    const uint32_t* hs2 = (const uint32_t*)hsm;

    for (int tile = blockIdx.x; tile < ntiles; tile += gridDim.x) {
        int e0 = tile * TEDGE;
        __syncthreads();  // previous tile's smem readers done (and w3j_s visible, 1st iter)

        if (tid < 128) {
            int e = e0 + (tid & 63);
            int which = tid >> 6;
            srcdst[tid] = (e < E) ? ei[which * E + e] : 0;
        }
        __syncthreads();
        for (int idx = tid; idx < TEDGE * 288; idx += NTHR) {
            int e = idx / 288;
            int c = idx - e * 288;
            xs[c * EPAD + e] = (e0 + e < E) ? nf[srcdst[e] * 288 + c] : 0.f;
        }
        for (int idx = tid; idx < TEDGE * 64; idx += NTHR) {
            int e = idx >> 6;
            int c = idx & 63;
            hsm[e * 64 + c] = (e0 + e < E) ? g_Hh[(e0 + e) * 64 + c] : __float2half(0.f);
        }
        for (int idx = tid; idx < TEDGE * 9; idx += NTHR) {
            int e = idx & 63;
            int j = idx >> 6;
            shT[j * EPAD + e] = (e0 + e < E) ? shg[(e0 + e) * 9 + j] : 0.f;
        }
        __syncthreads();  // hsm/xs/shT ready

        // A fragments (h, fp16 half2-packed)
        uint32_t af[4][4];
#pragma unroll
        for (int q = 0; q < 4; q++) {
            af[q][0] = hs2[er0 * 32 + q * 8 + tig];
            af[q][1] = hs2[er1 * 32 + q * 8 + tig];
            af[q][2] = hs2[er0 * 32 + q * 8 + 4 + tig];
            af[q][3] = hs2[er1 * 32 + q * 8 + 4 + tig];
        }

        float acc[4][9];
#pragma unroll
        for (int p = 0; p < 4; p++)
#pragma unroll
            for (int k = 0; k < 9; k++) acc[p][k] = 0.f;

        // Software pipeline: z(i) in buf(i&1); iter i: write z(i+1), mma(i), barrier.
        CZ(0, 0, 0, 0, zb0);
        __syncthreads();
        CZ(1, 0, 1, 1, zb1);   MP(0, 0, 0, 0, zb0);  __syncthreads();
        CZ(2, 0, 2, 2, zb0);   MP(1, 0, 1, 1, zb1);  __syncthreads();
        CZ(3, 1, 0, 1, zb1);   MP(2, 0, 2, 2, zb0);  __syncthreads();
        CZ(4, 1, 1, 0, zb0);   MP(3, 1, 0, 1, zb1);  __syncthreads();
        CZ(5, 1, 1, 2, zb1);   MP(4, 1, 1, 0, zb0);  __syncthreads();
        CZ(6, 1, 2, 1, zb0);   MP(5, 1, 1, 2, zb1);  __syncthreads();
        CZ(7, 2, 0, 2, zb1);   MP(6, 1, 2, 1, zb0);  __syncthreads();
        CZ(8, 2, 1, 1, zb0);   MP(7, 2, 0, 2, zb1);  __syncthreads();
        CZ(9, 2, 2, 0, zb1);   MP(8, 2, 1, 1, zb0);  __syncthreads();
        CZ(10, 2, 2, 2, zb0);  MP(9, 2, 2, 0, zb1);  __syncthreads();
        MP(10, 2, 2, 2, zb0);

        // Raw accumulation into g_agg (final_kernel applies 1/sqrt(10) + self-connection).
#pragma unroll
        for (int p = 0; p < 4; p++) {
            int e = (p & 2) ? er1 : er0;
            int wcol = (p & 1) ? wc1 : wc0;
            if (e0 + e >= E) continue;
            int node = srcdst[64 + e];
            float* op = g_agg + node * 288;
            float* ac = acc[p];
            atomicAdd(op + wcol, ac[0]);
#pragma unroll
            for (int k = 0; k < 3; k++) atomicAdd(op + 32 + wcol * 3 + k, ac[1 + k]);
#pragma unroll
            for (int k = 0; k < 5; k++) atomicAdd(op + 128 + wcol * 5 + k, ac[4 + k]);
        }
    }
}

// ======================= final: out = agg/sqrt(10) + self-connection; re-zero agg ==========
__global__ void final_kernel(const float* __restrict__ nf, const float* __restrict__ w0,
                             const float* __restrict__ w1, const float* __restrict__ w2,
                             float* __restrict__ out) {
    __shared__ float xrow[288];
    int n = blockIdx.x;
    int t = threadIdx.x;
    xrow[t] = nf[n * 288 + t];
    __syncthreads();
    int O, d, wch, k;
    const float* W;
    if (t < 32)       { O = 0;   d = 1; wch = t;          k = 0;            W = w0; }
    else if (t < 128) { int r = t - 32;  O = 32;  d = 3; wch = r / 3; k = r - wch * 3; W = w1; }
    else              { int r = t - 128; O = 128; d = 5; wch = r / 5; k = r - wch * 5; W = w2; }
    float a = 0.f;
#pragma unroll
    for (int u = 0; u < 32; u++) a += xrow[O + u * d + k] * W[u * 32 + wch];
    int oidx = n * 288 + t;
    float agg = g_agg[oidx];
    g_agg[oidx] = 0.f;  // reset for next graph replay
    out[oidx] = agg * 0.31622776601683794f + a * 0.17677669529663687f;
}

// ======================= host: numpy RandomState(0) SILU_CST reproduction =======================
namespace {
struct NpRng {
    uint32_t mt[624];
    int mti;
    bool has_g;
    double g;
};
inline void rng_seed(NpRng& s, uint32_t sd) {
    s.mt[0] = sd;
    for (int i = 1; i < 624; i++)
        s.mt[i] = 1812433253u * (s.mt[i - 1] ^ (s.mt[i - 1] >> 30)) + (uint32_t)i;
    s.mti = 624;
    s.has_g = false;
    s.g = 0.0;
}
inline uint32_t rng_u32(NpRng& s) {
    if (s.mti >= 624) {
        for (int i = 0; i < 624; i++) {
            uint32_t y = (s.mt[i] & 0x80000000u) | (s.mt[(i + 1) % 624] & 0x7fffffffu);
            s.mt[i] = s.mt[(i + 397) % 624] ^ (y >> 1) ^ ((y & 1u) ? 0x9908b0dfu : 0u);
        }
        s.mti = 0;
    }
    uint32_t y = s.mt[s.mti++];
    y ^= y >> 11;
    y ^= (y << 7) & 0x9d2c5680u;
    y ^= (y << 15) & 0xefc60000u;
    y ^= y >> 18;
    return y;
}
inline double rng_double(NpRng& s) {
    uint32_t a = rng_u32(s) >> 5;
    uint32_t b = rng_u32(s) >> 6;
    return ((double)a * 67108864.0 + (double)b) / 9007199254740992.0;
}
inline double rng_gauss(NpRng& s) {
    if (s.has_g) {
        s.has_g = false;
        return s.g;
    }
    double x1, x2, r2;
    do {
        x1 = 2.0 * rng_double(s) - 1.0;
        x2 = 2.0 * rng_double(s) - 1.0;
        r2 = x1 * x1 + x2 * x2;
    } while (r2 >= 1.0 || r2 == 0.0);
    double f = sqrt(-2.0 * log(r2) / r2);
    s.g = f * x1;
    s.has_g = true;
    return f * x2;
}
inline double compute_silu_cst() {
    NpRng s;
    rng_seed(s, 0u);
    double sum = 0.0;
    for (int i = 0; i < 1000000; i++) {
        double z = rng_gauss(s);
        double sl = z / (1.0 + exp(-z));
        sum += sl * sl;
    }
    return 1.0 / sqrt(sum / 1000000.0);
}
}  // namespace

// ======================= launch =======================
extern "C" void kernel_launch(void* const* d_in, const int* in_sizes, int n_in,
                              void* d_out, int out_size) {
    const float* nf     = (const float*)d_in[0];
    const int*   ei     = (const int*)d_in[1];
    const float* sh     = (const float*)d_in[2];
    const float* radial = (const float*)d_in[3];
    const float* W1     = (const float*)d_in[4];
    const float* W2     = (const float*)d_in[5];
    const float* Wsc0   = (const float*)d_in[6];
    const float* Wsc1   = (const float*)d_in[7];
    const float* Wsc2   = (const float*)d_in[8];
    float* out = (float*)d_out;
    int N = in_sizes[0] / 288;
    int E = in_sizes[1] / 2;

    float cst = (float)compute_silu_cst();

    const size_t SMEM = (288 * EPAD + TEDGE * 32 + 2 * 32 * 5 * EPAD + 9 * EPAD + 1375) * 4
                        + 128 * 4;  // ~175 KB
    cudaFuncSetAttribute(msg_kernel, cudaFuncAttributeMaxDynamicSharedMemorySize, (int)SMEM);

    int ntiles = (E + TEDGE - 1) / TEDGE;
    int nb = ntiles < 296 ? ntiles : 296;  // 2 waves at 1 block/SM on 148 SMs

    w3j_setup_kernel<<<11, 128>>>();
    w2h_kernel<<<(64 * 11264 + 255) / 256, 256>>>(W2);
    h_kernel<<<(E + 3) / 4, 256>>>(radial, W1, cst, E);
    msg_kernel<<<nb, NTHR, SMEM>>>(nf, ei, sh, E, ntiles);
    final_kernel<<<N, 288>>>(nf, Wsc0, Wsc1, Wsc2, out);
}